// round 2
// baseline (speedup 1.0000x reference)
#include <cuda_runtime.h>

// Problem constants
#define BB   16
#define CC   512
#define LL   2048
#define DQK  64
#define MQKV 640   // 64 q + 64 k + 512 v output channels

// ---------------- scratch (device globals; no dynamic allocation) ----------
__device__ float g_w[MQKV * CC];          // concat [wq; wk; wv]  [640,512]
__device__ float g_bias[MQKV];
__device__ float g_q[(size_t)BB * LL * DQK];   // [b][l][d]
__device__ float g_k[(size_t)BB * DQK * LL];   // [b][d][l]
__device__ float g_v[(size_t)BB * LL * CC];    // [b][l][c]
__device__ float g_av[(size_t)BB * LL * CC];   // [b][l][c]

// ---------------- kernel 0: concat weights --------------------------------
__global__ void prep_kernel(const float* __restrict__ wq, const float* __restrict__ bq,
                            const float* __restrict__ wk, const float* __restrict__ bk,
                            const float* __restrict__ wv, const float* __restrict__ bv) {
    int idx = blockIdx.x * blockDim.x + threadIdx.x;
    if (idx < MQKV * CC) {
        int row = idx >> 9;      // /512
        int c   = idx & 511;
        float val;
        if (row < 64)        val = wq[row * CC + c];
        else if (row < 128)  val = wk[(row - 64) * CC + c];
        else                 val = wv[(row - 128) * CC + c];
        g_w[idx] = val;
    }
    if (idx < MQKV) {
        float bv_;
        if (idx < 64)        bv_ = bq[idx];
        else if (idx < 128)  bv_ = bk[idx - 64];
        else                 bv_ = bv[idx - 128];
        g_bias[idx] = bv_;
    }
}

// ---------------- kernel 1: QKV projection GEMM ----------------------------
// Out[b,o,l] = sum_c g_w[o,c] * x[b,c,l] + g_bias[o]; scatter to q/k/v.
// Tile 64(o) x 64(l), K-chunk 16, 256 threads, 4x4 microtile.
__global__ __launch_bounds__(256) void qkv_kernel(const float* __restrict__ x) {
    int b  = blockIdx.z;
    int ot = blockIdx.y;   // 0..9
    int lt = blockIdx.x;   // 0..31
    int t  = threadIdx.x;
    int tx = t & 15, ty = t >> 4;

    __shared__ float As[16][68];   // [k][o]
    __shared__ float Bs[16][68];   // [k][l]

    float acc[4][4];
#pragma unroll
    for (int i = 0; i < 4; i++)
#pragma unroll
        for (int j = 0; j < 4; j++) acc[i][j] = 0.f;

    const float* xb = x + (size_t)b * CC * LL;

    for (int k0 = 0; k0 < CC; k0 += 16) {
        __syncthreads();
#pragma unroll
        for (int i = 0; i < 4; i++) {                 // 1024 elems
            int e = t + 256 * i;
            int kk = e & 15, o = e >> 4;
            As[kk][o] = g_w[(size_t)(ot * 64 + o) * CC + k0 + kk];
        }
#pragma unroll
        for (int i = 0; i < 4; i++) {
            int e = t + 256 * i;
            int kk = e >> 6, l = e & 63;
            Bs[kk][l] = xb[(size_t)(k0 + kk) * LL + lt * 64 + l];
        }
        __syncthreads();
#pragma unroll
        for (int kk = 0; kk < 16; kk++) {
            float a[4], bb[4];
#pragma unroll
            for (int i = 0; i < 4; i++) a[i] = As[kk][ty * 4 + i];
#pragma unroll
            for (int j = 0; j < 4; j++) bb[j] = Bs[kk][tx * 4 + j];
#pragma unroll
            for (int i = 0; i < 4; i++)
#pragma unroll
                for (int j = 0; j < 4; j++) acc[i][j] += a[i] * bb[j];
        }
    }

#pragma unroll
    for (int i = 0; i < 4; i++) {
        int o = ot * 64 + ty * 4 + i;
        float bias = g_bias[o];
#pragma unroll
        for (int j = 0; j < 4; j++) {
            int l = lt * 64 + tx * 4 + j;
            float val = acc[i][j] + bias;
            if (o < 64)
                g_q[((size_t)b * LL + l) * DQK + o] = val;
            else if (o < 128)
                g_k[((size_t)b * DQK + (o - 64)) * LL + l] = val;
            else
                g_v[((size_t)b * LL + l) * CC + (o - 128)] = val;
        }
    }
}

// ---------------- kernel 2: flash attention --------------------------------
// Per block: 64 queries x all 512 channels. Online softmax over 32 key blocks
// of 64. 256 threads; thread t owns q-row r=t>>2 and a quad-interleaved
// 128-channel set; 128 fp32 accumulators/thread.
#define SM_VS   0                     // [64][128]
#define SM_KS   (64 * 128)            // [64][64]  Ks[d][j]
#define SM_QS   (SM_KS + 64 * 64)     // [64][65]
#define SM_PS   (SM_QS + 64 * 65)     // [64][65]
#define SM_ATTN_FLOATS (SM_PS + 64 * 65)

__global__ __launch_bounds__(256, 1) void attn_kernel() {
    extern __shared__ __align__(16) float sm[];
    float* Vs = sm + SM_VS;
    float* Ks = sm + SM_KS;
    float* Qs = sm + SM_QS;
    float* Ps = sm + SM_PS;

    int b  = blockIdx.y;
    int qt = blockIdx.x;        // 0..31
    int t  = threadIdx.x;
    int lane4 = t & 3;
    int r     = t >> 2;         // q-row 0..63

    // load Q tile [64][64] -> Qs pitch 65
    const float* qb = g_q + ((size_t)b * LL + qt * 64) * DQK;
#pragma unroll
    for (int i = 0; i < 16; i++) {
        int e = t + 256 * i;
        int row = e >> 6, col = e & 63;
        Qs[row * 65 + col] = qb[e];
    }

    float m = -1e30f, lsum = 0.f;
    float acc[4][32];
#pragma unroll
    for (int c = 0; c < 4; c++)
#pragma unroll
        for (int i = 0; i < 32; i++) acc[c][i] = 0.f;

    for (int kb = 0; kb < 32; kb++) {
        __syncthreads();
        // load K tile: Ks[d][j] = g_k[b][d][kb*64+j]
        const float* kbp = g_k + (size_t)b * DQK * LL + kb * 64;
#pragma unroll
        for (int i = 0; i < 4; i++) {
            int e = t + 256 * i;            // float4 index, 64*16
            int d = e >> 4, j4 = e & 15;
            float4 vv = *(const float4*)(kbp + (size_t)d * LL + j4 * 4);
            *(float4*)(Ks + d * 64 + j4 * 4) = vv;
        }
        __syncthreads();

        // S: thread's 16 keys at j = lane4*4 + jj*16 + mi
        float s[16];
#pragma unroll
        for (int i = 0; i < 16; i++) s[i] = 0.f;
#pragma unroll 8
        for (int d = 0; d < 64; d++) {
            float qv = Qs[r * 65 + d];
#pragma unroll
            for (int jj = 0; jj < 4; jj++) {
                float4 kv = *(const float4*)(Ks + d * 64 + lane4 * 4 + jj * 16);
                s[jj * 4 + 0] += qv * kv.x;
                s[jj * 4 + 1] += qv * kv.y;
                s[jj * 4 + 2] += qv * kv.z;
                s[jj * 4 + 3] += qv * kv.w;
            }
        }
        // online softmax (row spread over a quad)
        float mx = s[0];
#pragma unroll
        for (int i = 1; i < 16; i++) mx = fmaxf(mx, s[i]);
        mx = fmaxf(mx, __shfl_xor_sync(0xffffffffu, mx, 1));
        mx = fmaxf(mx, __shfl_xor_sync(0xffffffffu, mx, 2));
        float mnew  = fmaxf(m, mx);
        float scale = __expf(m - mnew);
        float psum = 0.f;
#pragma unroll
        for (int i = 0; i < 16; i++) { s[i] = __expf(s[i] - mnew); psum += s[i]; }
        psum += __shfl_xor_sync(0xffffffffu, psum, 1);
        psum += __shfl_xor_sync(0xffffffffu, psum, 2);
        lsum = lsum * scale + psum;
        m = mnew;
#pragma unroll
        for (int jj = 0; jj < 4; jj++)
#pragma unroll
            for (int mi = 0; mi < 4; mi++)
                Ps[r * 65 + lane4 * 4 + jj * 16 + mi] = s[jj * 4 + mi];
#pragma unroll
        for (int c = 0; c < 4; c++)
#pragma unroll
            for (int i = 0; i < 32; i++) acc[c][i] *= scale;

        // AV: stream V through 128-channel chunks
#pragma unroll
        for (int cc = 0; cc < 4; cc++) {
            __syncthreads();   // prev chunk reads done (and Ps written for cc=0)
            const float* vbp = g_v + ((size_t)b * LL + kb * 64) * CC + cc * 128;
#pragma unroll
            for (int i = 0; i < 8; i++) {
                int e = t + 256 * i;        // float4 index, 64*32
                int row = e >> 5, c4 = e & 31;
                *(float4*)(Vs + row * 128 + c4 * 4) =
                    *(const float4*)(vbp + (size_t)row * CC + c4 * 4);
            }
            __syncthreads();
#pragma unroll 4
            for (int j = 0; j < 64; j++) {
                float p = Ps[r * 65 + j];
#pragma unroll
                for (int jj = 0; jj < 8; jj++) {
                    float4 vv = *(const float4*)(Vs + j * 128 + lane4 * 4 + jj * 16);
                    acc[cc][jj * 4 + 0] += p * vv.x;
                    acc[cc][jj * 4 + 1] += p * vv.y;
                    acc[cc][jj * 4 + 2] += p * vv.z;
                    acc[cc][jj * 4 + 3] += p * vv.w;
                }
            }
        }
    }

    // epilogue: av[b][l][c] = acc / lsum
    float inv = 1.f / lsum;
    float* avp = g_av + ((size_t)b * LL + qt * 64 + r) * CC;
#pragma unroll
    for (int cc = 0; cc < 4; cc++)
#pragma unroll
        for (int jj = 0; jj < 8; jj++) {
            float4 o;
            o.x = acc[cc][jj * 4 + 0] * inv;
            o.y = acc[cc][jj * 4 + 1] * inv;
            o.z = acc[cc][jj * 4 + 2] * inv;
            o.w = acc[cc][jj * 4 + 3] * inv;
            *(float4*)(avp + cc * 128 + lane4 * 4 + jj * 16) = o;
        }
}

// ---------------- kernel 3: output projection + residual -------------------
// out[b,o,l] = gamma*(sum_c wo[o,c]*av[b,l,c] + bo[o]) + x[b,o,l]
__global__ __launch_bounds__(256) void out_kernel(const float* __restrict__ wo,
                                                  const float* __restrict__ bo,
                                                  const float* __restrict__ x,
                                                  const float* __restrict__ gamma,
                                                  float* __restrict__ out) {
    int b  = blockIdx.z;
    int ot = blockIdx.y;   // 0..7
    int lt = blockIdx.x;   // 0..31
    int t  = threadIdx.x;
    int tx = t & 15, ty = t >> 4;

    __shared__ float As[16][68];   // [k][o]
    __shared__ float Bs[16][68];   // [k][l]

    float acc[4][4];
#pragma unroll
    for (int i = 0; i < 4; i++)
#pragma unroll
        for (int j = 0; j < 4; j++) acc[i][j] = 0.f;

    const float* avb = g_av + (size_t)b * LL * CC;

    for (int k0 = 0; k0 < CC; k0 += 16) {
        __syncthreads();
#pragma unroll
        for (int i = 0; i < 4; i++) {
            int e = t + 256 * i;
            int kk = e & 15, o = e >> 4;
            As[kk][o] = wo[(size_t)(ot * 64 + o) * CC + k0 + kk];
        }
#pragma unroll
        for (int i = 0; i < 4; i++) {
            int e = t + 256 * i;
            int kk = e & 15, l = e >> 4;
            Bs[kk][l] = avb[(size_t)(lt * 64 + l) * CC + k0 + kk];
        }
        __syncthreads();
#pragma unroll
        for (int kk = 0; kk < 16; kk++) {
            float a[4], bb[4];
#pragma unroll
            for (int i = 0; i < 4; i++) a[i] = As[kk][ty * 4 + i];
#pragma unroll
            for (int j = 0; j < 4; j++) bb[j] = Bs[kk][tx * 4 + j];
#pragma unroll
            for (int i = 0; i < 4; i++)
#pragma unroll
                for (int j = 0; j < 4; j++) acc[i][j] += a[i] * bb[j];
        }
    }

    float g = gamma[0];
#pragma unroll
    for (int i = 0; i < 4; i++) {
        int o = ot * 64 + ty * 4 + i;
        float bw = bo[o];
        size_t rowbase = ((size_t)b * CC + o) * LL + lt * 64 + tx * 4;
        float4 xv = *(const float4*)(x + rowbase);
        float4 ov;
        ov.x = g * (acc[i][0] + bw) + xv.x;
        ov.y = g * (acc[i][1] + bw) + xv.y;
        ov.z = g * (acc[i][2] + bw) + xv.z;
        ov.w = g * (acc[i][3] + bw) + xv.w;
        *(float4*)(out + rowbase) = ov;
    }
}

// ---------------- launch ----------------------------------------------------
extern "C" void kernel_launch(void* const* d_in, const int* in_sizes, int n_in,
                              void* d_out, int out_size) {
    const float* x     = (const float*)d_in[0];
    const float* wq    = (const float*)d_in[1];
    const float* bq    = (const float*)d_in[2];
    const float* wk    = (const float*)d_in[3];
    const float* bk    = (const float*)d_in[4];
    const float* wv    = (const float*)d_in[5];
    const float* bv    = (const float*)d_in[6];
    const float* wo    = (const float*)d_in[7];
    const float* bo    = (const float*)d_in[8];
    const float* gamma = (const float*)d_in[9];
    float* out = (float*)d_out;

    // Unconditional (no static guards); idempotent and capture-safe.
    cudaFuncSetAttribute(attn_kernel, cudaFuncAttributeMaxDynamicSharedMemorySize,
                         SM_ATTN_FLOATS * sizeof(float));

    prep_kernel<<<(MQKV * CC + 255) / 256, 256>>>(wq, bq, wk, bk, wv, bv);

    dim3 g1(LL / 64, MQKV / 64, BB);
    qkv_kernel<<<g1, 256>>>(x);

    dim3 g2(LL / 64, BB);
    attn_kernel<<<g2, 256, SM_ATTN_FLOATS * sizeof(float)>>>();

    dim3 g3(LL / 64, CC / 64, BB);
    out_kernel<<<g3, 256>>>(wo, bo, x, gamma, out);
}

// round 4
// speedup vs baseline: 3.7594x; 3.7594x over previous
#include <cuda_runtime.h>
#include <cuda_bf16.h>
#include <cstdint>

// Problem constants
#define BB   16
#define CC   512
#define LL   2048
#define DQK  64
#define MQKV 640   // 64 q + 64 k + 512 v output channels

// ---------------- scratch (device globals; no dynamic allocation) ----------
__device__ float g_w[MQKV * CC];          // concat [wq; wk; wv]  [640,512]
__device__ float g_bias[MQKV];
__device__ __nv_bfloat16 g_qb[(size_t)BB * LL * DQK];   // [b][l][d]
__device__ __nv_bfloat16 g_kb[(size_t)BB * LL * DQK];   // [b][l][d]
__device__ __nv_bfloat16 g_vb[(size_t)BB * LL * CC];    // [b][l][c]
__device__ float g_av[(size_t)BB * LL * CC];            // [b][l][c]

// ---------------- kernel 0: concat weights --------------------------------
__global__ void prep_kernel(const float* __restrict__ wq, const float* __restrict__ bq,
                            const float* __restrict__ wk, const float* __restrict__ bk,
                            const float* __restrict__ wv, const float* __restrict__ bv) {
    int idx = blockIdx.x * blockDim.x + threadIdx.x;
    if (idx < MQKV * CC) {
        int row = idx >> 9;      // /512
        int c   = idx & 511;
        float val;
        if (row < 64)        val = wq[row * CC + c];
        else if (row < 128)  val = wk[(row - 64) * CC + c];
        else                 val = wv[(row - 128) * CC + c];
        g_w[idx] = val;
    }
    if (idx < MQKV) {
        float bv_;
        if (idx < 64)        bv_ = bq[idx];
        else if (idx < 128)  bv_ = bk[idx - 64];
        else                 bv_ = bv[idx - 128];
        g_bias[idx] = bv_;
    }
}

// ---------------- kernel 1: QKV projection GEMM ----------------------------
// Out[b,o,l] = sum_c g_w[o,c] * x[b,c,l] + g_bias[o]; scatter (bf16) to q/k/v.
// Tile 64(o) x 64(l), K-chunk 16, 256 threads, 4x4 microtile.
// Note: each 64-row o-tile lies entirely in q (ot=0), k (ot=1) or v (ot>=2).
__global__ __launch_bounds__(256) void qkv_kernel(const float* __restrict__ x) {
    int b  = blockIdx.z;
    int ot = blockIdx.y;   // 0..9
    int lt = blockIdx.x;   // 0..31
    int t  = threadIdx.x;
    int tx = t & 15, ty = t >> 4;

    __shared__ float As[16][68];   // [k][o]
    __shared__ float Bs[16][68];   // [k][l]

    float acc[4][4];
#pragma unroll
    for (int i = 0; i < 4; i++)
#pragma unroll
        for (int j = 0; j < 4; j++) acc[i][j] = 0.f;

    const float* xb = x + (size_t)b * CC * LL;

    for (int k0 = 0; k0 < CC; k0 += 16) {
        __syncthreads();
#pragma unroll
        for (int i = 0; i < 4; i++) {                 // 1024 elems
            int e = t + 256 * i;
            int kk = e & 15, o = e >> 4;
            As[kk][o] = g_w[(size_t)(ot * 64 + o) * CC + k0 + kk];
        }
#pragma unroll
        for (int i = 0; i < 4; i++) {
            int e = t + 256 * i;
            int kk = e >> 6, l = e & 63;
            Bs[kk][l] = xb[(size_t)(k0 + kk) * LL + lt * 64 + l];
        }
        __syncthreads();
#pragma unroll
        for (int kk = 0; kk < 16; kk++) {
            float a[4], bb[4];
#pragma unroll
            for (int i = 0; i < 4; i++) a[i] = As[kk][ty * 4 + i];
#pragma unroll
            for (int j = 0; j < 4; j++) bb[j] = Bs[kk][tx * 4 + j];
#pragma unroll
            for (int i = 0; i < 4; i++)
#pragma unroll
                for (int j = 0; j < 4; j++) acc[i][j] += a[i] * bb[j];
        }
    }

    int o0 = ot * 64 + ty * 4;
    float bias[4];
#pragma unroll
    for (int i = 0; i < 4; i++) bias[i] = g_bias[o0 + i];

#pragma unroll
    for (int j = 0; j < 4; j++) {
        int l = lt * 64 + tx * 4 + j;
        __nv_bfloat16 vals[4];
#pragma unroll
        for (int i = 0; i < 4; i++) vals[i] = __float2bfloat16(acc[i][j] + bias[i]);
        uint2 pk = *(const uint2*)vals;
        if (ot == 0) {
            *(uint2*)(g_qb + ((size_t)b * LL + l) * DQK + o0) = pk;
        } else if (ot == 1) {
            *(uint2*)(g_kb + ((size_t)b * LL + l) * DQK + (o0 - 64)) = pk;
        } else {
            *(uint2*)(g_vb + ((size_t)b * LL + l) * CC + (o0 - 128)) = pk;
        }
    }
}

// ---------------- kernel 2: flash attention (bf16 HMMA) --------------------
// Block: 64 queries x 512 channels, 8 warps = 4 row-groups x 2 col-halves.
// S = Q K^T via mma.m16n8k16 (K frags from non-trans ldmatrix on n-major K).
// P stays in registers (C-frag -> bf16 A-frag). AV via mma with V B-frags
// from ldmatrix.x4.trans (V stored k-major).
#define QS_PITCH 72     // bf16 elems; 144B rows -> ldmatrix conflict-free
#define VS_PITCH 520    // bf16 elems; 1040B rows -> ldmatrix conflict-free
#define SMO_QS 0
#define SMO_KS (64 * QS_PITCH)
#define SMO_VS (SMO_KS + 64 * QS_PITCH)
#define SM_ATTN_BF16 (SMO_VS + 64 * VS_PITCH)
#define SM_ATTN_BYTES (SM_ATTN_BF16 * 2)

__device__ __forceinline__ uint32_t pack_bf16x2(float lo, float hi) {
    uint32_t r;
    asm volatile("cvt.rn.bf16x2.f32 %0, %1, %2;" : "=r"(r) : "f"(hi), "f"(lo));
    return r;
}

__device__ __forceinline__ void ldsm_x4(uint32_t& d0, uint32_t& d1, uint32_t& d2,
                                        uint32_t& d3, uint32_t addr) {
    asm volatile("ldmatrix.sync.aligned.m8n8.x4.shared.b16 {%0,%1,%2,%3}, [%4];"
                 : "=r"(d0), "=r"(d1), "=r"(d2), "=r"(d3) : "r"(addr));
}
__device__ __forceinline__ void ldsm_x4_trans(uint32_t& d0, uint32_t& d1, uint32_t& d2,
                                              uint32_t& d3, uint32_t addr) {
    asm volatile("ldmatrix.sync.aligned.m8n8.x4.trans.shared.b16 {%0,%1,%2,%3}, [%4];"
                 : "=r"(d0), "=r"(d1), "=r"(d2), "=r"(d3) : "r"(addr));
}
__device__ __forceinline__ void mma_bf16(float& c0, float& c1, float& c2, float& c3,
                                         uint32_t a0, uint32_t a1, uint32_t a2, uint32_t a3,
                                         uint32_t b0, uint32_t b1) {
    asm volatile("mma.sync.aligned.m16n8k16.row.col.f32.bf16.bf16.f32 "
                 "{%0,%1,%2,%3}, {%4,%5,%6,%7}, {%8,%9}, {%0,%1,%2,%3};"
                 : "+f"(c0), "+f"(c1), "+f"(c2), "+f"(c3)
                 : "r"(a0), "r"(a1), "r"(a2), "r"(a3), "r"(b0), "r"(b1));
}

__global__ __launch_bounds__(256, 1) void attn_kernel() {
    extern __shared__ __align__(16) __nv_bfloat16 sm[];
    __nv_bfloat16* Qs = sm + SMO_QS;
    __nv_bfloat16* Ks = sm + SMO_KS;
    __nv_bfloat16* Vs = sm + SMO_VS;

    int b  = blockIdx.y;
    int qt = blockIdx.x;
    int t  = threadIdx.x;
    int w  = t >> 5, l = t & 31;
    int wm = w & 3;      // row group: rows wm*16 .. +15
    int wn = w >> 2;     // col half: cols wn*256 .. +255

    // --- load Q tile [64][64] bf16 into Qs (pitch 72) ---
    {
        const uint4* qg = (const uint4*)(g_qb + ((size_t)b * LL + qt * 64) * DQK);
#pragma unroll
        for (int i = 0; i < 2; i++) {
            int e = t + 256 * i;             // 512 16B-chunks
            int row = e >> 3, c = e & 7;
            *(uint4*)(Qs + row * QS_PITCH + c * 8) = qg[row * 8 + c];
        }
    }
    __syncthreads();

    // --- persistent Q A-fragments: qa[kk][0..3], kk = k16 step ---
    uint32_t qa[4][4];
    {
        uint32_t base = (uint32_t)__cvta_generic_to_shared(Qs)
                      + (uint32_t)((wm * 16 + (l & 7) + 8 * ((l >> 3) & 1)) * (QS_PITCH * 2))
                      + 16 * ((l >> 4) & 1);
#pragma unroll
        for (int kk = 0; kk < 4; kk++)
            ldsm_x4(qa[kk][0], qa[kk][1], qa[kk][2], qa[kk][3], base + kk * 32);
    }

    // ldmatrix lane bases for K (non-trans) and V (trans)
    uint32_t ks_base = (uint32_t)__cvta_generic_to_shared(Ks)
                     + (uint32_t)(((l & 7) + 8 * ((l >> 4) & 1)) * (QS_PITCH * 2))
                     + 16 * ((l >> 3) & 1);
    uint32_t vs_base = (uint32_t)__cvta_generic_to_shared(Vs)
                     + (uint32_t)(((l & 7) + 8 * ((l >> 3) & 1)) * (VS_PITCH * 2))
                     + 16 * ((l >> 4) & 1);

    float m_lo = -1e30f, m_hi = -1e30f, ls_lo = 0.f, ls_hi = 0.f;
    float acc[32][4];
#pragma unroll
    for (int n = 0; n < 32; n++)
#pragma unroll
        for (int i = 0; i < 4; i++) acc[n][i] = 0.f;

    for (int kb = 0; kb < 32; kb++) {
        __syncthreads();
        // load K tile [64][64] bf16 (pitch 72) and V tile [64][512] bf16 (pitch 520)
        {
            const uint4* kg = (const uint4*)(g_kb + ((size_t)b * LL + kb * 64) * DQK);
#pragma unroll
            for (int i = 0; i < 2; i++) {
                int e = t + 256 * i;
                int row = e >> 3, c = e & 7;
                *(uint4*)(Ks + row * QS_PITCH + c * 8) = kg[row * 8 + c];
            }
            const uint4* vg = (const uint4*)(g_vb + ((size_t)b * LL + kb * 64) * CC);
#pragma unroll
            for (int i = 0; i < 16; i++) {
                int e = t + 256 * i;             // 4096 16B-chunks
                int row = e >> 6, c = e & 63;
                *(uint4*)(Vs + row * VS_PITCH + c * 8) = vg[row * 64 + c];
            }
        }
        __syncthreads();

        // --- S = Q K^T : sacc[nt][0..3], nt = n8 tile over 64 keys ---
        float sacc[8][4];
#pragma unroll
        for (int nt = 0; nt < 8; nt++)
#pragma unroll
            for (int i = 0; i < 4; i++) sacc[nt][i] = 0.f;

#pragma unroll
        for (int kk = 0; kk < 4; kk++) {
#pragma unroll
            for (int ntp = 0; ntp < 4; ntp++) {       // ntile pair
                uint32_t d0, d1, d2, d3;
                ldsm_x4(d0, d1, d2, d3, ks_base + ntp * 16 * (QS_PITCH * 2) + kk * 32);
                mma_bf16(sacc[2 * ntp][0], sacc[2 * ntp][1], sacc[2 * ntp][2], sacc[2 * ntp][3],
                         qa[kk][0], qa[kk][1], qa[kk][2], qa[kk][3], d0, d1);
                mma_bf16(sacc[2 * ntp + 1][0], sacc[2 * ntp + 1][1], sacc[2 * ntp + 1][2], sacc[2 * ntp + 1][3],
                         qa[kk][0], qa[kk][1], qa[kk][2], qa[kk][3], d2, d3);
            }
        }

        // --- online softmax (rows r = wm*16 + l/4 and r+8) ---
        float mx_lo = -1e30f, mx_hi = -1e30f;
#pragma unroll
        for (int nt = 0; nt < 8; nt++) {
            mx_lo = fmaxf(mx_lo, fmaxf(sacc[nt][0], sacc[nt][1]));
            mx_hi = fmaxf(mx_hi, fmaxf(sacc[nt][2], sacc[nt][3]));
        }
        mx_lo = fmaxf(mx_lo, __shfl_xor_sync(0xffffffffu, mx_lo, 1));
        mx_lo = fmaxf(mx_lo, __shfl_xor_sync(0xffffffffu, mx_lo, 2));
        mx_hi = fmaxf(mx_hi, __shfl_xor_sync(0xffffffffu, mx_hi, 1));
        mx_hi = fmaxf(mx_hi, __shfl_xor_sync(0xffffffffu, mx_hi, 2));

        float mn_lo = fmaxf(m_lo, mx_lo), mn_hi = fmaxf(m_hi, mx_hi);
        float sc_lo = __expf(m_lo - mn_lo), sc_hi = __expf(m_hi - mn_hi);
        m_lo = mn_lo; m_hi = mn_hi;

        float ps_lo = 0.f, ps_hi = 0.f;
#pragma unroll
        for (int nt = 0; nt < 8; nt++) {
            sacc[nt][0] = __expf(sacc[nt][0] - mn_lo);
            sacc[nt][1] = __expf(sacc[nt][1] - mn_lo);
            sacc[nt][2] = __expf(sacc[nt][2] - mn_hi);
            sacc[nt][3] = __expf(sacc[nt][3] - mn_hi);
            ps_lo += sacc[nt][0] + sacc[nt][1];
            ps_hi += sacc[nt][2] + sacc[nt][3];
        }
        ps_lo += __shfl_xor_sync(0xffffffffu, ps_lo, 1);
        ps_lo += __shfl_xor_sync(0xffffffffu, ps_lo, 2);
        ps_hi += __shfl_xor_sync(0xffffffffu, ps_hi, 1);
        ps_hi += __shfl_xor_sync(0xffffffffu, ps_hi, 2);
        ls_lo = ls_lo * sc_lo + ps_lo;
        ls_hi = ls_hi * sc_hi + ps_hi;

#pragma unroll
        for (int n = 0; n < 32; n++) {
            acc[n][0] *= sc_lo; acc[n][1] *= sc_lo;
            acc[n][2] *= sc_hi; acc[n][3] *= sc_hi;
        }

        // --- AV: P (A-frags from sacc) x V (B-frags via ldmatrix.trans) ---
#pragma unroll
        for (int kk = 0; kk < 4; kk++) {
            uint32_t pa0 = pack_bf16x2(sacc[2 * kk][0],     sacc[2 * kk][1]);
            uint32_t pa1 = pack_bf16x2(sacc[2 * kk][2],     sacc[2 * kk][3]);
            uint32_t pa2 = pack_bf16x2(sacc[2 * kk + 1][0], sacc[2 * kk + 1][1]);
            uint32_t pa3 = pack_bf16x2(sacc[2 * kk + 1][2], sacc[2 * kk + 1][3]);
            uint32_t vrow = vs_base + kk * 16 * (VS_PITCH * 2);
#pragma unroll
            for (int vt = 0; vt < 16; vt++) {         // 16-col pairs over this half
                uint32_t d0, d1, d2, d3;
                ldsm_x4_trans(d0, d1, d2, d3, vrow + (wn * 256 + vt * 16) * 2);
                mma_bf16(acc[2 * vt][0], acc[2 * vt][1], acc[2 * vt][2], acc[2 * vt][3],
                         pa0, pa1, pa2, pa3, d0, d1);
                mma_bf16(acc[2 * vt + 1][0], acc[2 * vt + 1][1], acc[2 * vt + 1][2], acc[2 * vt + 1][3],
                         pa0, pa1, pa2, pa3, d2, d3);
            }
        }
    }

    // --- epilogue: normalize, write g_av fp32 [b][l][512] ---
    float inv_lo = 1.f / ls_lo, inv_hi = 1.f / ls_hi;
    int row_lo = qt * 64 + wm * 16 + (l >> 2);
    int col0   = wn * 256 + 2 * (l & 3);
    float* av_lo = g_av + ((size_t)b * LL + row_lo) * CC;
    float* av_hi = av_lo + 8 * CC;
#pragma unroll
    for (int nt = 0; nt < 32; nt++) {
        int c = col0 + nt * 8;
        float2 vlo = { acc[nt][0] * inv_lo, acc[nt][1] * inv_lo };
        float2 vhi = { acc[nt][2] * inv_hi, acc[nt][3] * inv_hi };
        *(float2*)(av_lo + c) = vlo;
        *(float2*)(av_hi + c) = vhi;
    }
}

// ---------------- kernel 3: output projection + residual -------------------
// out[b,o,l] = gamma*(sum_c wo[o,c]*av[b,l,c] + bo[o]) + x[b,o,l]
__global__ __launch_bounds__(256) void out_kernel(const float* __restrict__ wo,
                                                  const float* __restrict__ bo,
                                                  const float* __restrict__ x,
                                                  const float* __restrict__ gamma,
                                                  float* __restrict__ out) {
    int b  = blockIdx.z;
    int ot = blockIdx.y;   // 0..7
    int lt = blockIdx.x;   // 0..31
    int t  = threadIdx.x;
    int tx = t & 15, ty = t >> 4;

    __shared__ float As[16][68];   // [k][o]
    __shared__ float Bs[16][68];   // [k][l]

    float acc[4][4];
#pragma unroll
    for (int i = 0; i < 4; i++)
#pragma unroll
        for (int j = 0; j < 4; j++) acc[i][j] = 0.f;

    const float* avb = g_av + (size_t)b * LL * CC;

    for (int k0 = 0; k0 < CC; k0 += 16) {
        __syncthreads();
#pragma unroll
        for (int i = 0; i < 4; i++) {
            int e = t + 256 * i;
            int kk = e & 15, o = e >> 4;
            As[kk][o] = wo[(size_t)(ot * 64 + o) * CC + k0 + kk];
        }
#pragma unroll
        for (int i = 0; i < 4; i++) {
            int e = t + 256 * i;
            int kk = e & 15, l = e >> 4;
            Bs[kk][l] = avb[(size_t)(lt * 64 + l) * CC + k0 + kk];
        }
        __syncthreads();
#pragma unroll
        for (int kk = 0; kk < 16; kk++) {
            float a[4], bb[4];
#pragma unroll
            for (int i = 0; i < 4; i++) a[i] = As[kk][ty * 4 + i];
#pragma unroll
            for (int j = 0; j < 4; j++) bb[j] = Bs[kk][tx * 4 + j];
#pragma unroll
            for (int i = 0; i < 4; i++)
#pragma unroll
                for (int j = 0; j < 4; j++) acc[i][j] += a[i] * bb[j];
        }
    }

    float g = gamma[0];
#pragma unroll
    for (int i = 0; i < 4; i++) {
        int o = ot * 64 + ty * 4 + i;
        float bw = bo[o];
        size_t rowbase = ((size_t)b * CC + o) * LL + lt * 64 + tx * 4;
        float4 xv = *(const float4*)(x + rowbase);
        float4 ov;
        ov.x = g * (acc[i][0] + bw) + xv.x;
        ov.y = g * (acc[i][1] + bw) + xv.y;
        ov.z = g * (acc[i][2] + bw) + xv.z;
        ov.w = g * (acc[i][3] + bw) + xv.w;
        *(float4*)(out + rowbase) = ov;
    }
}

// ---------------- launch ----------------------------------------------------
extern "C" void kernel_launch(void* const* d_in, const int* in_sizes, int n_in,
                              void* d_out, int out_size) {
    const float* x     = (const float*)d_in[0];
    const float* wq    = (const float*)d_in[1];
    const float* bq    = (const float*)d_in[2];
    const float* wk    = (const float*)d_in[3];
    const float* bk    = (const float*)d_in[4];
    const float* wv    = (const float*)d_in[5];
    const float* bv    = (const float*)d_in[6];
    const float* wo    = (const float*)d_in[7];
    const float* bo    = (const float*)d_in[8];
    const float* gamma = (const float*)d_in[9];
    float* out = (float*)d_out;

    // Unconditional (no static guards); idempotent and capture-safe.
    cudaFuncSetAttribute(attn_kernel, cudaFuncAttributeMaxDynamicSharedMemorySize,
                         SM_ATTN_BYTES);

    prep_kernel<<<(MQKV * CC + 255) / 256, 256>>>(wq, bq, wk, bk, wv, bv);

    dim3 g1(LL / 64, MQKV / 64, BB);
    qkv_kernel<<<g1, 256>>>(x);

    dim3 g2(LL / 64, BB);
    attn_kernel<<<g2, 256, SM_ATTN_BYTES>>>();

    dim3 g3(LL / 64, CC / 64, BB);
    out_kernel<<<g3, 256>>>(wo, bo, x, gamma, out);
}

// round 5
// speedup vs baseline: 10.5914x; 2.8173x over previous
#include <cuda_runtime.h>
#include <cuda_bf16.h>
#include <cstdint>

// Problem constants
#define BB   16
#define CC   512
#define LL   2048
#define DQK  64
#define MQKV 640   // 64 q + 64 k + 512 v output channels

// ---------------- scratch (device globals; no dynamic allocation) ----------
__device__ float g_bias[MQKV];
__device__ __nv_bfloat16 g_wb[MQKV * CC];               // [o][c] bf16 qkv weights
__device__ __nv_bfloat16 g_wob[CC * CC];                // [o][c] bf16 wo
__device__ __nv_bfloat16 g_xb[(size_t)BB * CC * LL];    // [b][c][l] bf16
__device__ __nv_bfloat16 g_qb[(size_t)BB * LL * DQK];   // [b][l][d]
__device__ __nv_bfloat16 g_kb[(size_t)BB * LL * DQK];   // [b][l][d]
__device__ __nv_bfloat16 g_vb[(size_t)BB * LL * CC];    // [b][l][c]
__device__ __nv_bfloat16 g_avb[(size_t)BB * LL * CC];   // [b][l][c]

// ---------------- helpers ---------------------------------------------------
__device__ __forceinline__ uint32_t pack_bf16x2(float lo, float hi) {
    uint32_t r;
    asm volatile("cvt.rn.bf16x2.f32 %0, %1, %2;" : "=r"(r) : "f"(hi), "f"(lo));
    return r;
}
__device__ __forceinline__ void ldsm_x4(uint32_t& d0, uint32_t& d1, uint32_t& d2,
                                        uint32_t& d3, uint32_t addr) {
    asm volatile("ldmatrix.sync.aligned.m8n8.x4.shared.b16 {%0,%1,%2,%3}, [%4];"
                 : "=r"(d0), "=r"(d1), "=r"(d2), "=r"(d3) : "r"(addr));
}
__device__ __forceinline__ void ldsm_x4_trans(uint32_t& d0, uint32_t& d1, uint32_t& d2,
                                              uint32_t& d3, uint32_t addr) {
    asm volatile("ldmatrix.sync.aligned.m8n8.x4.trans.shared.b16 {%0,%1,%2,%3}, [%4];"
                 : "=r"(d0), "=r"(d1), "=r"(d2), "=r"(d3) : "r"(addr));
}
__device__ __forceinline__ void mma_bf16(float& c0, float& c1, float& c2, float& c3,
                                         uint32_t a0, uint32_t a1, uint32_t a2, uint32_t a3,
                                         uint32_t b0, uint32_t b1) {
    asm volatile("mma.sync.aligned.m16n8k16.row.col.f32.bf16.bf16.f32 "
                 "{%0,%1,%2,%3}, {%4,%5,%6,%7}, {%8,%9}, {%0,%1,%2,%3};"
                 : "+f"(c0), "+f"(c1), "+f"(c2), "+f"(c3)
                 : "r"(a0), "r"(a1), "r"(a2), "r"(a3), "r"(b0), "r"(b1));
}

// ---------------- kernel 0a: weights -> bf16, bias concat -------------------
__global__ void prep_kernel(const float* __restrict__ wq, const float* __restrict__ bq,
                            const float* __restrict__ wk, const float* __restrict__ bk,
                            const float* __restrict__ wv, const float* __restrict__ bv,
                            const float* __restrict__ wo) {
    int idx = blockIdx.x * blockDim.x + threadIdx.x;
    if (idx < MQKV * CC) {
        int row = idx >> 9;
        int c   = idx & 511;
        float val;
        if (row < 64)        val = wq[row * CC + c];
        else if (row < 128)  val = wk[(row - 64) * CC + c];
        else                 val = wv[(row - 128) * CC + c];
        g_wb[idx] = __float2bfloat16(val);
    }
    if (idx < CC * CC) g_wob[idx] = __float2bfloat16(wo[idx]);
    if (idx < MQKV) {
        float bv_;
        if (idx < 64)        bv_ = bq[idx];
        else if (idx < 128)  bv_ = bk[idx - 64];
        else                 bv_ = bv[idx - 128];
        g_bias[idx] = bv_;
    }
}

// ---------------- kernel 0b: x -> bf16 --------------------------------------
__global__ __launch_bounds__(256) void xconv_kernel(const float* __restrict__ x) {
    size_t i = (size_t)blockIdx.x * 256 + threadIdx.x;   // float4 index
    float4 v = ((const float4*)x)[i];
    uint2 pk;
    pk.x = pack_bf16x2(v.x, v.y);
    pk.y = pack_bf16x2(v.z, v.w);
    *(uint2*)(g_xb + 4 * i) = pk;
}

// ---------------- kernel 1: QKV projection (bf16 HMMA) ----------------------
// C[l, o] = sum_c X[c,l] * W[o,c]; block 128 l x 128 o, k-chunks of 64.
// A = X^T via trans-ldmatrix on [k][l] tile; B = W via non-trans on [o][k].
#define XS_PITCH 136
#define WS_PITCH 72
__global__ __launch_bounds__(256) void qkv_kernel() {
    int b  = blockIdx.z;
    int ot = blockIdx.y;   // 0..4 (o tile of 128)
    int lt = blockIdx.x;   // 0..15 (l tile of 128)
    int t  = threadIdx.x;
    int w  = t >> 5, ln = t & 31;
    int wm = w & 3;        // l sub-tile (32 rows)
    int wn = w >> 2;       // o sub-tile (64 cols)

    __shared__ __align__(16) __nv_bfloat16 Xs[64 * XS_PITCH];
    __shared__ __align__(16) __nv_bfloat16 Ws[128 * WS_PITCH];

    float acc[2][8][4];
#pragma unroll
    for (int mt = 0; mt < 2; mt++)
#pragma unroll
        for (int nt = 0; nt < 8; nt++)
#pragma unroll
            for (int i = 0; i < 4; i++) acc[mt][nt][i] = 0.f;

    int o0 = ot * 128;
    uint32_t xa_base = (uint32_t)__cvta_generic_to_shared(Xs)
                     + (uint32_t)(((ln & 7) + 8 * ((ln >> 3) & 1)) * (XS_PITCH * 2))
                     + 16 * ((ln >> 4) & 1) + (uint32_t)(wm * 32 * 2);
    uint32_t ws_base = (uint32_t)__cvta_generic_to_shared(Ws)
                     + (uint32_t)(((ln & 7) + 8 * ((ln >> 4) & 1)) * (WS_PITCH * 2))
                     + 16 * ((ln >> 3) & 1) + (uint32_t)(wn * 64 * (WS_PITCH * 2));

    for (int k0 = 0; k0 < CC; k0 += 64) {
        __syncthreads();
        {
            const uint4* xg = (const uint4*)(g_xb + ((size_t)b * CC + k0) * LL + lt * 128);
#pragma unroll
            for (int i = 0; i < 4; i++) {
                int e = t + 256 * i;          // 1024 chunks: 64 rows x 16
                int row = e >> 4, c = e & 15;
                *(uint4*)(Xs + row * XS_PITCH + c * 8) = xg[row * 256 + c];
            }
            const uint4* wg = (const uint4*)(g_wb + (size_t)o0 * CC + k0);
#pragma unroll
            for (int i = 0; i < 4; i++) {
                int e = t + 256 * i;          // 1024 chunks: 128 rows x 8
                int row = e >> 3, c = e & 7;
                *(uint4*)(Ws + row * WS_PITCH + c * 8) = wg[row * 64 + c];
            }
        }
        __syncthreads();
#pragma unroll
        for (int kk = 0; kk < 4; kk++) {
            uint32_t ta[2][4];
#pragma unroll
            for (int mt = 0; mt < 2; mt++)
                ldsm_x4_trans(ta[mt][0], ta[mt][1], ta[mt][2], ta[mt][3],
                              xa_base + kk * 16 * (XS_PITCH * 2) + mt * 16 * 2);
#pragma unroll
            for (int ntp = 0; ntp < 4; ntp++) {
                uint32_t b0, b1, b2, b3;
                ldsm_x4(b0, b1, b2, b3, ws_base + ntp * 16 * (WS_PITCH * 2) + kk * 32);
#pragma unroll
                for (int mt = 0; mt < 2; mt++) {
                    // A-frag order from trans load: a0=d0, a1=d2, a2=d1, a3=d3
                    mma_bf16(acc[mt][2 * ntp][0], acc[mt][2 * ntp][1],
                             acc[mt][2 * ntp][2], acc[mt][2 * ntp][3],
                             ta[mt][0], ta[mt][2], ta[mt][1], ta[mt][3], b0, b1);
                    mma_bf16(acc[mt][2 * ntp + 1][0], acc[mt][2 * ntp + 1][1],
                             acc[mt][2 * ntp + 1][2], acc[mt][2 * ntp + 1][3],
                             ta[mt][0], ta[mt][2], ta[mt][1], ta[mt][3], b2, b3);
                }
            }
        }
    }

    // epilogue: scatter bf16 pairs to q/k/v [b][l][*]
    int og0 = o0 + wn * 64;
    __nv_bfloat16* dst;
    int dstride, doff;
    if (og0 == 0)       { dst = g_qb + (size_t)b * LL * DQK; dstride = DQK; doff = 0; }
    else if (og0 == 64) { dst = g_kb + (size_t)b * LL * DQK; dstride = DQK; doff = 0; }
    else                { dst = g_vb + (size_t)b * LL * CC;  dstride = CC;  doff = og0 - 128; }

    int cl = 2 * (ln & 3);
    float bias_lo[8], bias_hi[8];
#pragma unroll
    for (int nt = 0; nt < 8; nt++) {
        bias_lo[nt] = g_bias[og0 + nt * 8 + cl];
        bias_hi[nt] = g_bias[og0 + nt * 8 + cl + 1];
    }
#pragma unroll
    for (int mt = 0; mt < 2; mt++) {
        int row = lt * 128 + wm * 32 + mt * 16 + (ln >> 2);
#pragma unroll
        for (int nt = 0; nt < 8; nt++) {
            uint32_t p0 = pack_bf16x2(acc[mt][nt][0] + bias_lo[nt],
                                      acc[mt][nt][1] + bias_hi[nt]);
            uint32_t p1 = pack_bf16x2(acc[mt][nt][2] + bias_lo[nt],
                                      acc[mt][nt][3] + bias_hi[nt]);
            *(uint32_t*)(dst + (size_t)row * dstride + doff + nt * 8 + cl) = p0;
            *(uint32_t*)(dst + (size_t)(row + 8) * dstride + doff + nt * 8 + cl) = p1;
        }
    }
}

// ---------------- kernel 2: flash attention (bf16 HMMA) --------------------
#define QS_PITCH 72     // bf16 elems; 144B rows -> ldmatrix conflict-free
#define VS_PITCH 520    // bf16 elems; 1040B rows -> ldmatrix conflict-free
#define SMO_QS 0
#define SMO_KS (64 * QS_PITCH)
#define SMO_VS (SMO_KS + 64 * QS_PITCH)
#define SM_ATTN_BF16 (SMO_VS + 64 * VS_PITCH)
#define SM_ATTN_BYTES (SM_ATTN_BF16 * 2)

__global__ __launch_bounds__(256, 1) void attn_kernel() {
    extern __shared__ __align__(16) __nv_bfloat16 sm[];
    __nv_bfloat16* Qs = sm + SMO_QS;
    __nv_bfloat16* Ks = sm + SMO_KS;
    __nv_bfloat16* Vs = sm + SMO_VS;

    int b  = blockIdx.y;
    int qt = blockIdx.x;
    int t  = threadIdx.x;
    int w  = t >> 5, l = t & 31;
    int wm = w & 3;
    int wn = w >> 2;

    {
        const uint4* qg = (const uint4*)(g_qb + ((size_t)b * LL + qt * 64) * DQK);
#pragma unroll
        for (int i = 0; i < 2; i++) {
            int e = t + 256 * i;
            int row = e >> 3, c = e & 7;
            *(uint4*)(Qs + row * QS_PITCH + c * 8) = qg[row * 8 + c];
        }
    }
    __syncthreads();

    uint32_t qa[4][4];
    {
        uint32_t base = (uint32_t)__cvta_generic_to_shared(Qs)
                      + (uint32_t)((wm * 16 + (l & 7) + 8 * ((l >> 3) & 1)) * (QS_PITCH * 2))
                      + 16 * ((l >> 4) & 1);
#pragma unroll
        for (int kk = 0; kk < 4; kk++)
            ldsm_x4(qa[kk][0], qa[kk][1], qa[kk][2], qa[kk][3], base + kk * 32);
    }

    uint32_t ks_base = (uint32_t)__cvta_generic_to_shared(Ks)
                     + (uint32_t)(((l & 7) + 8 * ((l >> 4) & 1)) * (QS_PITCH * 2))
                     + 16 * ((l >> 3) & 1);
    uint32_t vs_base = (uint32_t)__cvta_generic_to_shared(Vs)
                     + (uint32_t)(((l & 7) + 8 * ((l >> 3) & 1)) * (VS_PITCH * 2))
                     + 16 * ((l >> 4) & 1);

    float m_lo = -1e30f, m_hi = -1e30f, ls_lo = 0.f, ls_hi = 0.f;
    float acc[32][4];
#pragma unroll
    for (int n = 0; n < 32; n++)
#pragma unroll
        for (int i = 0; i < 4; i++) acc[n][i] = 0.f;

    for (int kb = 0; kb < 32; kb++) {
        __syncthreads();
        {
            const uint4* kg = (const uint4*)(g_kb + ((size_t)b * LL + kb * 64) * DQK);
#pragma unroll
            for (int i = 0; i < 2; i++) {
                int e = t + 256 * i;
                int row = e >> 3, c = e & 7;
                *(uint4*)(Ks + row * QS_PITCH + c * 8) = kg[row * 8 + c];
            }
            const uint4* vg = (const uint4*)(g_vb + ((size_t)b * LL + kb * 64) * CC);
#pragma unroll
            for (int i = 0; i < 16; i++) {
                int e = t + 256 * i;
                int row = e >> 6, c = e & 63;
                *(uint4*)(Vs + row * VS_PITCH + c * 8) = vg[row * 64 + c];
            }
        }
        __syncthreads();

        float sacc[8][4];
#pragma unroll
        for (int nt = 0; nt < 8; nt++)
#pragma unroll
            for (int i = 0; i < 4; i++) sacc[nt][i] = 0.f;

#pragma unroll
        for (int kk = 0; kk < 4; kk++) {
#pragma unroll
            for (int ntp = 0; ntp < 4; ntp++) {
                uint32_t d0, d1, d2, d3;
                ldsm_x4(d0, d1, d2, d3, ks_base + ntp * 16 * (QS_PITCH * 2) + kk * 32);
                mma_bf16(sacc[2 * ntp][0], sacc[2 * ntp][1], sacc[2 * ntp][2], sacc[2 * ntp][3],
                         qa[kk][0], qa[kk][1], qa[kk][2], qa[kk][3], d0, d1);
                mma_bf16(sacc[2 * ntp + 1][0], sacc[2 * ntp + 1][1], sacc[2 * ntp + 1][2], sacc[2 * ntp + 1][3],
                         qa[kk][0], qa[kk][1], qa[kk][2], qa[kk][3], d2, d3);
            }
        }

        float mx_lo = -1e30f, mx_hi = -1e30f;
#pragma unroll
        for (int nt = 0; nt < 8; nt++) {
            mx_lo = fmaxf(mx_lo, fmaxf(sacc[nt][0], sacc[nt][1]));
            mx_hi = fmaxf(mx_hi, fmaxf(sacc[nt][2], sacc[nt][3]));
        }
        mx_lo = fmaxf(mx_lo, __shfl_xor_sync(0xffffffffu, mx_lo, 1));
        mx_lo = fmaxf(mx_lo, __shfl_xor_sync(0xffffffffu, mx_lo, 2));
        mx_hi = fmaxf(mx_hi, __shfl_xor_sync(0xffffffffu, mx_hi, 1));
        mx_hi = fmaxf(mx_hi, __shfl_xor_sync(0xffffffffu, mx_hi, 2));

        float mn_lo = fmaxf(m_lo, mx_lo), mn_hi = fmaxf(m_hi, mx_hi);
        float sc_lo = __expf(m_lo - mn_lo), sc_hi = __expf(m_hi - mn_hi);
        m_lo = mn_lo; m_hi = mn_hi;

        float ps_lo = 0.f, ps_hi = 0.f;
#pragma unroll
        for (int nt = 0; nt < 8; nt++) {
            sacc[nt][0] = __expf(sacc[nt][0] - mn_lo);
            sacc[nt][1] = __expf(sacc[nt][1] - mn_lo);
            sacc[nt][2] = __expf(sacc[nt][2] - mn_hi);
            sacc[nt][3] = __expf(sacc[nt][3] - mn_hi);
            ps_lo += sacc[nt][0] + sacc[nt][1];
            ps_hi += sacc[nt][2] + sacc[nt][3];
        }
        ps_lo += __shfl_xor_sync(0xffffffffu, ps_lo, 1);
        ps_lo += __shfl_xor_sync(0xffffffffu, ps_lo, 2);
        ps_hi += __shfl_xor_sync(0xffffffffu, ps_hi, 1);
        ps_hi += __shfl_xor_sync(0xffffffffu, ps_hi, 2);
        ls_lo = ls_lo * sc_lo + ps_lo;
        ls_hi = ls_hi * sc_hi + ps_hi;

#pragma unroll
        for (int n = 0; n < 32; n++) {
            acc[n][0] *= sc_lo; acc[n][1] *= sc_lo;
            acc[n][2] *= sc_hi; acc[n][3] *= sc_hi;
        }

#pragma unroll
        for (int kk = 0; kk < 4; kk++) {
            uint32_t pa0 = pack_bf16x2(sacc[2 * kk][0],     sacc[2 * kk][1]);
            uint32_t pa1 = pack_bf16x2(sacc[2 * kk][2],     sacc[2 * kk][3]);
            uint32_t pa2 = pack_bf16x2(sacc[2 * kk + 1][0], sacc[2 * kk + 1][1]);
            uint32_t pa3 = pack_bf16x2(sacc[2 * kk + 1][2], sacc[2 * kk + 1][3]);
            uint32_t vrow = vs_base + kk * 16 * (VS_PITCH * 2);
#pragma unroll
            for (int vt = 0; vt < 16; vt++) {
                uint32_t d0, d1, d2, d3;
                ldsm_x4_trans(d0, d1, d2, d3, vrow + (wn * 256 + vt * 16) * 2);
                mma_bf16(acc[2 * vt][0], acc[2 * vt][1], acc[2 * vt][2], acc[2 * vt][3],
                         pa0, pa1, pa2, pa3, d0, d1);
                mma_bf16(acc[2 * vt + 1][0], acc[2 * vt + 1][1], acc[2 * vt + 1][2], acc[2 * vt + 1][3],
                         pa0, pa1, pa2, pa3, d2, d3);
            }
        }
    }

    // epilogue: normalize, write bf16 av [b][l][512]
    float inv_lo = 1.f / ls_lo, inv_hi = 1.f / ls_hi;
    int row_lo = qt * 64 + wm * 16 + (l >> 2);
    int col0   = wn * 256 + 2 * (l & 3);
    __nv_bfloat16* av_lo = g_avb + ((size_t)b * LL + row_lo) * CC;
    __nv_bfloat16* av_hi = av_lo + 8 * CC;
#pragma unroll
    for (int nt = 0; nt < 32; nt++) {
        int c = col0 + nt * 8;
        *(uint32_t*)(av_lo + c) = pack_bf16x2(acc[nt][0] * inv_lo, acc[nt][1] * inv_lo);
        *(uint32_t*)(av_hi + c) = pack_bf16x2(acc[nt][2] * inv_hi, acc[nt][3] * inv_hi);
    }
}

// ---------------- kernel 3: output projection (bf16 HMMA) + residual -------
// C[o, l] = sum_c wo[o,c] * av[l,c]; out = gamma*(C + bo) + x.
__global__ __launch_bounds__(256) void out_kernel(const float* __restrict__ x,
                                                  const float* __restrict__ bo,
                                                  const float* __restrict__ gamma,
                                                  float* __restrict__ out) {
    int b  = blockIdx.z;
    int ot = blockIdx.y;   // 0..3 (o tile of 128)
    int lt = blockIdx.x;   // 0..15 (l tile of 128)
    int t  = threadIdx.x;
    int w  = t >> 5, ln = t & 31;
    int wm = w & 3;        // o sub-tile (32 rows)
    int wn = w >> 2;       // l sub-tile (64 cols)

    __shared__ __align__(16) __nv_bfloat16 As_[128 * WS_PITCH];
    __shared__ __align__(16) __nv_bfloat16 Bs_[128 * WS_PITCH];

    float acc[2][8][4];
#pragma unroll
    for (int mt = 0; mt < 2; mt++)
#pragma unroll
        for (int nt = 0; nt < 8; nt++)
#pragma unroll
            for (int i = 0; i < 4; i++) acc[mt][nt][i] = 0.f;

    int o0 = ot * 128;
    uint32_t ab = (uint32_t)__cvta_generic_to_shared(As_)
                + (uint32_t)(((ln & 7) + 8 * ((ln >> 3) & 1)) * (WS_PITCH * 2))
                + 16 * ((ln >> 4) & 1) + (uint32_t)(wm * 32 * (WS_PITCH * 2));
    uint32_t bb = (uint32_t)__cvta_generic_to_shared(Bs_)
                + (uint32_t)(((ln & 7) + 8 * ((ln >> 4) & 1)) * (WS_PITCH * 2))
                + 16 * ((ln >> 3) & 1) + (uint32_t)(wn * 64 * (WS_PITCH * 2));

    for (int k0 = 0; k0 < CC; k0 += 64) {
        __syncthreads();
        {
            const uint4* ag = (const uint4*)(g_wob + (size_t)o0 * CC + k0);
            const uint4* bg = (const uint4*)(g_avb + ((size_t)b * LL + lt * 128) * CC + k0);
#pragma unroll
            for (int i = 0; i < 4; i++) {
                int e = t + 256 * i;
                int row = e >> 3, c = e & 7;
                *(uint4*)(As_ + row * WS_PITCH + c * 8) = ag[row * 64 + c];
                *(uint4*)(Bs_ + row * WS_PITCH + c * 8) = bg[row * 64 + c];
            }
        }
        __syncthreads();
#pragma unroll
        for (int kk = 0; kk < 4; kk++) {
            uint32_t a[2][4];
#pragma unroll
            for (int mt = 0; mt < 2; mt++)
                ldsm_x4(a[mt][0], a[mt][1], a[mt][2], a[mt][3],
                        ab + mt * 16 * (WS_PITCH * 2) + kk * 32);
#pragma unroll
            for (int ntp = 0; ntp < 4; ntp++) {
                uint32_t b0, b1, b2, b3;
                ldsm_x4(b0, b1, b2, b3, bb + ntp * 16 * (WS_PITCH * 2) + kk * 32);
#pragma unroll
                for (int mt = 0; mt < 2; mt++) {
                    mma_bf16(acc[mt][2 * ntp][0], acc[mt][2 * ntp][1],
                             acc[mt][2 * ntp][2], acc[mt][2 * ntp][3],
                             a[mt][0], a[mt][1], a[mt][2], a[mt][3], b0, b1);
                    mma_bf16(acc[mt][2 * ntp + 1][0], acc[mt][2 * ntp + 1][1],
                             acc[mt][2 * ntp + 1][2], acc[mt][2 * ntp + 1][3],
                             a[mt][0], a[mt][1], a[mt][2], a[mt][3], b2, b3);
                }
            }
        }
    }

    float g = gamma[0];
    int cl = 2 * (ln & 3);
#pragma unroll
    for (int mt = 0; mt < 2; mt++) {
        int o_r = o0 + wm * 32 + mt * 16 + (ln >> 2);
        float b0v = bo[o_r], b1v = bo[o_r + 8];
#pragma unroll
        for (int nt = 0; nt < 8; nt++) {
            int lc = lt * 128 + wn * 64 + nt * 8 + cl;
            size_t base0 = ((size_t)b * CC + o_r) * LL + lc;
            size_t base1 = base0 + (size_t)8 * LL;
            float2 xv0 = *(const float2*)(x + base0);
            float2 xv1 = *(const float2*)(x + base1);
            float2 r0, r1;
            r0.x = g * (acc[mt][nt][0] + b0v) + xv0.x;
            r0.y = g * (acc[mt][nt][1] + b0v) + xv0.y;
            r1.x = g * (acc[mt][nt][2] + b1v) + xv1.x;
            r1.y = g * (acc[mt][nt][3] + b1v) + xv1.y;
            *(float2*)(out + base0) = r0;
            *(float2*)(out + base1) = r1;
        }
    }
}

// ---------------- launch ----------------------------------------------------
extern "C" void kernel_launch(void* const* d_in, const int* in_sizes, int n_in,
                              void* d_out, int out_size) {
    const float* x     = (const float*)d_in[0];
    const float* wq    = (const float*)d_in[1];
    const float* bq    = (const float*)d_in[2];
    const float* wk    = (const float*)d_in[3];
    const float* bk    = (const float*)d_in[4];
    const float* wv    = (const float*)d_in[5];
    const float* bv    = (const float*)d_in[6];
    const float* wo    = (const float*)d_in[7];
    const float* bo    = (const float*)d_in[8];
    const float* gamma = (const float*)d_in[9];
    float* out = (float*)d_out;

    cudaFuncSetAttribute(attn_kernel, cudaFuncAttributeMaxDynamicSharedMemorySize,
                         SM_ATTN_BYTES);

    prep_kernel<<<(CC * CC + 255) / 256 + 256, 256>>>(wq, bq, wk, bk, wv, bv, wo);
    xconv_kernel<<<((size_t)BB * CC * LL / 4) / 256, 256>>>(x);

    dim3 g1(LL / 128, MQKV / 128, BB);
    qkv_kernel<<<g1, 256>>>();

    dim3 g2(LL / 64, BB);
    attn_kernel<<<g2, 256, SM_ATTN_BYTES>>>();

    dim3 g3(LL / 128, CC / 128, BB);
    out_kernel<<<g3, 256>>>(x, bo, gamma, out);
}

// round 6
// speedup vs baseline: 11.5171x; 1.0874x over previous
#include <cuda_runtime.h>
#include <cuda_bf16.h>
#include <cstdint>

// Problem constants
#define BB   16
#define CC   512
#define LL   2048
#define DQK  64
#define MQKV 640   // 64 q + 64 k + 512 v output channels

// ---------------- scratch (device globals; no dynamic allocation) ----------
__device__ float g_bias[MQKV];
__device__ __nv_bfloat16 g_wb[MQKV * CC];               // [o][c] bf16 qkv weights
__device__ __nv_bfloat16 g_wob[CC * CC];                // [o][c] bf16 wo
__device__ __nv_bfloat16 g_xb[(size_t)BB * CC * LL];    // [b][c][l] bf16
__device__ __nv_bfloat16 g_qb[(size_t)BB * LL * DQK];   // [b][l][d]
__device__ __nv_bfloat16 g_kb[(size_t)BB * LL * DQK];   // [b][l][d]
__device__ __nv_bfloat16 g_vb[(size_t)BB * LL * CC];    // [b][l][c]
__device__ __nv_bfloat16 g_avb[(size_t)BB * LL * CC];   // [b][l][c]

// ---------------- helpers ---------------------------------------------------
__device__ __forceinline__ uint32_t pack_bf16x2(float lo, float hi) {
    uint32_t r;
    asm volatile("cvt.rn.bf16x2.f32 %0, %1, %2;" : "=r"(r) : "f"(hi), "f"(lo));
    return r;
}
__device__ __forceinline__ void ldsm_x4(uint32_t& d0, uint32_t& d1, uint32_t& d2,
                                        uint32_t& d3, uint32_t addr) {
    asm volatile("ldmatrix.sync.aligned.m8n8.x4.shared.b16 {%0,%1,%2,%3}, [%4];"
                 : "=r"(d0), "=r"(d1), "=r"(d2), "=r"(d3) : "r"(addr));
}
__device__ __forceinline__ void ldsm_x4_trans(uint32_t& d0, uint32_t& d1, uint32_t& d2,
                                              uint32_t& d3, uint32_t addr) {
    asm volatile("ldmatrix.sync.aligned.m8n8.x4.trans.shared.b16 {%0,%1,%2,%3}, [%4];"
                 : "=r"(d0), "=r"(d1), "=r"(d2), "=r"(d3) : "r"(addr));
}
__device__ __forceinline__ void mma_bf16(float& c0, float& c1, float& c2, float& c3,
                                         uint32_t a0, uint32_t a1, uint32_t a2, uint32_t a3,
                                         uint32_t b0, uint32_t b1) {
    asm volatile("mma.sync.aligned.m16n8k16.row.col.f32.bf16.bf16.f32 "
                 "{%0,%1,%2,%3}, {%4,%5,%6,%7}, {%8,%9}, {%0,%1,%2,%3};"
                 : "+f"(c0), "+f"(c1), "+f"(c2), "+f"(c3)
                 : "r"(a0), "r"(a1), "r"(a2), "r"(a3), "r"(b0), "r"(b1));
}
__device__ __forceinline__ void cp_async16(uint32_t smem_addr, const void* gptr) {
    asm volatile("cp.async.cg.shared.global [%0], [%1], 16;"
                 :: "r"(smem_addr), "l"(gptr));
}
__device__ __forceinline__ void cp_commit() {
    asm volatile("cp.async.commit_group;");
}
template <int N> __device__ __forceinline__ void cp_wait() {
    asm volatile("cp.async.wait_group %0;" :: "n"(N));
}

// ---------------- kernel 0a: weights -> bf16, bias concat -------------------
__global__ void prep_kernel(const float* __restrict__ wq, const float* __restrict__ bq,
                            const float* __restrict__ wk, const float* __restrict__ bk,
                            const float* __restrict__ wv, const float* __restrict__ bv,
                            const float* __restrict__ wo) {
    int idx = blockIdx.x * blockDim.x + threadIdx.x;
    if (idx < MQKV * CC) {
        int row = idx >> 9;
        int c   = idx & 511;
        float val;
        if (row < 64)        val = wq[row * CC + c];
        else if (row < 128)  val = wk[(row - 64) * CC + c];
        else                 val = wv[(row - 128) * CC + c];
        g_wb[idx] = __float2bfloat16(val);
    }
    if (idx < CC * CC) g_wob[idx] = __float2bfloat16(wo[idx]);
    if (idx < MQKV) {
        float bv_;
        if (idx < 64)        bv_ = bq[idx];
        else if (idx < 128)  bv_ = bk[idx - 64];
        else                 bv_ = bv[idx - 128];
        g_bias[idx] = bv_;
    }
}

// ---------------- kernel 0b: x -> bf16 --------------------------------------
__global__ __launch_bounds__(256) void xconv_kernel(const float* __restrict__ x) {
    size_t i = (size_t)blockIdx.x * 256 + threadIdx.x;   // float4 index
    float4 v = ((const float4*)x)[i];
    uint2 pk;
    pk.x = pack_bf16x2(v.x, v.y);
    pk.y = pack_bf16x2(v.z, v.w);
    *(uint2*)(g_xb + 4 * i) = pk;
}

// ---------------- kernel 1: QKV projection (bf16 HMMA) ----------------------
// C[l, o] = sum_c X[c,l] * W[o,c]; block 128 l x 128 o, k-chunks of 64.
#define XS_PITCH 136
#define WS_PITCH 72
__global__ __launch_bounds__(256) void qkv_kernel() {
    int b  = blockIdx.z;
    int ot = blockIdx.y;   // 0..4
    int lt = blockIdx.x;   // 0..15
    int t  = threadIdx.x;
    int w  = t >> 5, ln = t & 31;
    int wm = w & 3;
    int wn = w >> 2;

    __shared__ __align__(16) __nv_bfloat16 Xs[64 * XS_PITCH];
    __shared__ __align__(16) __nv_bfloat16 Ws[128 * WS_PITCH];

    float acc[2][8][4];
#pragma unroll
    for (int mt = 0; mt < 2; mt++)
#pragma unroll
        for (int nt = 0; nt < 8; nt++)
#pragma unroll
            for (int i = 0; i < 4; i++) acc[mt][nt][i] = 0.f;

    int o0 = ot * 128;
    uint32_t xa_base = (uint32_t)__cvta_generic_to_shared(Xs)
                     + (uint32_t)(((ln & 7) + 8 * ((ln >> 3) & 1)) * (XS_PITCH * 2))
                     + 16 * ((ln >> 4) & 1) + (uint32_t)(wm * 32 * 2);
    uint32_t ws_base = (uint32_t)__cvta_generic_to_shared(Ws)
                     + (uint32_t)(((ln & 7) + 8 * ((ln >> 4) & 1)) * (WS_PITCH * 2))
                     + 16 * ((ln >> 3) & 1) + (uint32_t)(wn * 64 * (WS_PITCH * 2));

    for (int k0 = 0; k0 < CC; k0 += 64) {
        __syncthreads();
        {
            const uint4* xg = (const uint4*)(g_xb + ((size_t)b * CC + k0) * LL + lt * 128);
#pragma unroll
            for (int i = 0; i < 4; i++) {
                int e = t + 256 * i;
                int row = e >> 4, c = e & 15;
                *(uint4*)(Xs + row * XS_PITCH + c * 8) = xg[row * 256 + c];
            }
            const uint4* wg = (const uint4*)(g_wb + (size_t)o0 * CC + k0);
#pragma unroll
            for (int i = 0; i < 4; i++) {
                int e = t + 256 * i;
                int row = e >> 3, c = e & 7;
                *(uint4*)(Ws + row * WS_PITCH + c * 8) = wg[row * 64 + c];
            }
        }
        __syncthreads();
#pragma unroll
        for (int kk = 0; kk < 4; kk++) {
            uint32_t ta[2][4];
#pragma unroll
            for (int mt = 0; mt < 2; mt++)
                ldsm_x4_trans(ta[mt][0], ta[mt][1], ta[mt][2], ta[mt][3],
                              xa_base + kk * 16 * (XS_PITCH * 2) + mt * 16 * 2);
#pragma unroll
            for (int ntp = 0; ntp < 4; ntp++) {
                uint32_t b0, b1, b2, b3;
                ldsm_x4(b0, b1, b2, b3, ws_base + ntp * 16 * (WS_PITCH * 2) + kk * 32);
#pragma unroll
                for (int mt = 0; mt < 2; mt++) {
                    mma_bf16(acc[mt][2 * ntp][0], acc[mt][2 * ntp][1],
                             acc[mt][2 * ntp][2], acc[mt][2 * ntp][3],
                             ta[mt][0], ta[mt][2], ta[mt][1], ta[mt][3], b0, b1);
                    mma_bf16(acc[mt][2 * ntp + 1][0], acc[mt][2 * ntp + 1][1],
                             acc[mt][2 * ntp + 1][2], acc[mt][2 * ntp + 1][3],
                             ta[mt][0], ta[mt][2], ta[mt][1], ta[mt][3], b2, b3);
                }
            }
        }
    }

    int og0 = o0 + wn * 64;
    __nv_bfloat16* dst;
    int dstride, doff;
    if (og0 == 0)       { dst = g_qb + (size_t)b * LL * DQK; dstride = DQK; doff = 0; }
    else if (og0 == 64) { dst = g_kb + (size_t)b * LL * DQK; dstride = DQK; doff = 0; }
    else                { dst = g_vb + (size_t)b * LL * CC;  dstride = CC;  doff = og0 - 128; }

    int cl = 2 * (ln & 3);
    float bias_lo[8], bias_hi[8];
#pragma unroll
    for (int nt = 0; nt < 8; nt++) {
        bias_lo[nt] = g_bias[og0 + nt * 8 + cl];
        bias_hi[nt] = g_bias[og0 + nt * 8 + cl + 1];
    }
#pragma unroll
    for (int mt = 0; mt < 2; mt++) {
        int row = lt * 128 + wm * 32 + mt * 16 + (ln >> 2);
#pragma unroll
        for (int nt = 0; nt < 8; nt++) {
            uint32_t p0 = pack_bf16x2(acc[mt][nt][0] + bias_lo[nt],
                                      acc[mt][nt][1] + bias_hi[nt]);
            uint32_t p1 = pack_bf16x2(acc[mt][nt][2] + bias_lo[nt],
                                      acc[mt][nt][3] + bias_hi[nt]);
            *(uint32_t*)(dst + (size_t)row * dstride + doff + nt * 8 + cl) = p0;
            *(uint32_t*)(dst + (size_t)(row + 8) * dstride + doff + nt * 8 + cl) = p1;
        }
    }
}

// ---------------- kernel 2: flash attention (bf16 HMMA, cp.async 2-stage) ---
#define QS_PITCH 72     // bf16; 144B rows
#define VS_PITCH 520    // bf16; 1040B rows
#define SMO_QS  0
#define SMO_KS0 (64 * QS_PITCH)
#define SMO_KS1 (SMO_KS0 + 64 * QS_PITCH)
#define SMO_VS0 (SMO_KS1 + 64 * QS_PITCH)
#define SMO_VS1 (SMO_VS0 + 64 * VS_PITCH)
#define SM_ATTN_BF16 (SMO_VS1 + 64 * VS_PITCH)
#define SM_ATTN_BYTES (SM_ATTN_BF16 * 2)

__global__ __launch_bounds__(256, 1) void attn_kernel() {
    extern __shared__ __align__(16) __nv_bfloat16 sm[];
    uint32_t smem_u32 = (uint32_t)__cvta_generic_to_shared(sm);

    int b  = blockIdx.y;
    int qt = blockIdx.x;
    int t  = threadIdx.x;
    int w  = t >> 5, l = t & 31;
    int wm = w & 3;
    int wn = w >> 2;

    const char* kg_base = (const char*)(g_kb + (size_t)b * LL * DQK);
    const char* vg_base = (const char*)(g_vb + (size_t)b * LL * CC);

    // per-thread load coordinates
    int krow = t >> 3, kcol = t & 7;          // K: 512 chunks over 2 iters
    int vrow = t >> 6, vcol = t & 63;         // V: 4096 chunks over 16 iters

    // issue cp.async group for key-block kb into buffer bf
    auto issue_tile = [&](int kb, int bf) {
        const char* kg = kg_base + (size_t)kb * 64 * DQK * 2;
        uint32_t ks = smem_u32 + (bf ? SMO_KS1 : SMO_KS0) * 2;
#pragma unroll
        for (int i = 0; i < 2; i++) {
            int row = krow + 32 * i;
            cp_async16(ks + row * (QS_PITCH * 2) + kcol * 16,
                       kg + row * (DQK * 2) + kcol * 16);
        }
        const char* vg = vg_base + (size_t)kb * 64 * CC * 2;
        uint32_t vs = smem_u32 + (bf ? SMO_VS1 : SMO_VS0) * 2;
#pragma unroll
        for (int i = 0; i < 16; i++) {
            int row = vrow + 4 * i;
            cp_async16(vs + row * (VS_PITCH * 2) + vcol * 16,
                       vg + row * (CC * 2) + vcol * 16);
        }
        cp_commit();
    };

    // --- load Q tile [64][64] -> Qs, build persistent A-frags ---
    {
        const uint4* qg = (const uint4*)(g_qb + ((size_t)b * LL + qt * 64) * DQK);
        __nv_bfloat16* Qs = sm + SMO_QS;
#pragma unroll
        for (int i = 0; i < 2; i++) {
            int e = t + 256 * i;
            int row = e >> 3, c = e & 7;
            *(uint4*)(Qs + row * QS_PITCH + c * 8) = qg[row * 8 + c];
        }
    }
    // prologue: async-load tile 0
    issue_tile(0, 0);
    __syncthreads();

    uint32_t qa[4][4];
    {
        uint32_t base = smem_u32 + SMO_QS * 2
                      + (uint32_t)((wm * 16 + (l & 7) + 8 * ((l >> 3) & 1)) * (QS_PITCH * 2))
                      + 16 * ((l >> 4) & 1);
#pragma unroll
        for (int kk = 0; kk < 4; kk++)
            ldsm_x4(qa[kk][0], qa[kk][1], qa[kk][2], qa[kk][3], base + kk * 32);
    }

    uint32_t ks_lane = (uint32_t)(((l & 7) + 8 * ((l >> 4) & 1)) * (QS_PITCH * 2))
                     + 16 * ((l >> 3) & 1);
    uint32_t vs_lane = (uint32_t)(((l & 7) + 8 * ((l >> 3) & 1)) * (VS_PITCH * 2))
                     + 16 * ((l >> 4) & 1);
    uint32_t ks_b[2] = { smem_u32 + SMO_KS0 * 2 + ks_lane, smem_u32 + SMO_KS1 * 2 + ks_lane };
    uint32_t vs_b[2] = { smem_u32 + SMO_VS0 * 2 + vs_lane, smem_u32 + SMO_VS1 * 2 + vs_lane };

    float m_lo = -1e30f, m_hi = -1e30f, ls_lo = 0.f, ls_hi = 0.f;
    float acc[32][4];
#pragma unroll
    for (int n = 0; n < 32; n++)
#pragma unroll
        for (int i = 0; i < 4; i++) acc[n][i] = 0.f;

    for (int kb = 0; kb < 32; kb++) {
        int cur = kb & 1;
        if (kb + 1 < 32) issue_tile(kb + 1, cur ^ 1);
        else             cp_commit();          // empty group keeps count aligned
        cp_wait<1>();                          // tile kb's group complete
        __syncthreads();

        uint32_t ks_base = ks_b[cur];
        uint32_t vs_base = vs_b[cur];

        // --- S = Q K^T ---
        float sacc[8][4];
#pragma unroll
        for (int nt = 0; nt < 8; nt++)
#pragma unroll
            for (int i = 0; i < 4; i++) sacc[nt][i] = 0.f;

#pragma unroll
        for (int kk = 0; kk < 4; kk++) {
#pragma unroll
            for (int ntp = 0; ntp < 4; ntp++) {
                uint32_t d0, d1, d2, d3;
                ldsm_x4(d0, d1, d2, d3, ks_base + ntp * 16 * (QS_PITCH * 2) + kk * 32);
                mma_bf16(sacc[2 * ntp][0], sacc[2 * ntp][1], sacc[2 * ntp][2], sacc[2 * ntp][3],
                         qa[kk][0], qa[kk][1], qa[kk][2], qa[kk][3], d0, d1);
                mma_bf16(sacc[2 * ntp + 1][0], sacc[2 * ntp + 1][1], sacc[2 * ntp + 1][2], sacc[2 * ntp + 1][3],
                         qa[kk][0], qa[kk][1], qa[kk][2], qa[kk][3], d2, d3);
            }
        }

        // --- online softmax ---
        float mx_lo = -1e30f, mx_hi = -1e30f;
#pragma unroll
        for (int nt = 0; nt < 8; nt++) {
            mx_lo = fmaxf(mx_lo, fmaxf(sacc[nt][0], sacc[nt][1]));
            mx_hi = fmaxf(mx_hi, fmaxf(sacc[nt][2], sacc[nt][3]));
        }
        mx_lo = fmaxf(mx_lo, __shfl_xor_sync(0xffffffffu, mx_lo, 1));
        mx_lo = fmaxf(mx_lo, __shfl_xor_sync(0xffffffffu, mx_lo, 2));
        mx_hi = fmaxf(mx_hi, __shfl_xor_sync(0xffffffffu, mx_hi, 1));
        mx_hi = fmaxf(mx_hi, __shfl_xor_sync(0xffffffffu, mx_hi, 2));

        float mn_lo = fmaxf(m_lo, mx_lo), mn_hi = fmaxf(m_hi, mx_hi);
        float sc_lo = __expf(m_lo - mn_lo), sc_hi = __expf(m_hi - mn_hi);
        m_lo = mn_lo; m_hi = mn_hi;

        float ps_lo = 0.f, ps_hi = 0.f;
#pragma unroll
        for (int nt = 0; nt < 8; nt++) {
            sacc[nt][0] = __expf(sacc[nt][0] - mn_lo);
            sacc[nt][1] = __expf(sacc[nt][1] - mn_lo);
            sacc[nt][2] = __expf(sacc[nt][2] - mn_hi);
            sacc[nt][3] = __expf(sacc[nt][3] - mn_hi);
            ps_lo += sacc[nt][0] + sacc[nt][1];
            ps_hi += sacc[nt][2] + sacc[nt][3];
        }
        ps_lo += __shfl_xor_sync(0xffffffffu, ps_lo, 1);
        ps_lo += __shfl_xor_sync(0xffffffffu, ps_lo, 2);
        ps_hi += __shfl_xor_sync(0xffffffffu, ps_hi, 1);
        ps_hi += __shfl_xor_sync(0xffffffffu, ps_hi, 2);
        ls_lo = ls_lo * sc_lo + ps_lo;
        ls_hi = ls_hi * sc_hi + ps_hi;

#pragma unroll
        for (int n = 0; n < 32; n++) {
            acc[n][0] *= sc_lo; acc[n][1] *= sc_lo;
            acc[n][2] *= sc_hi; acc[n][3] *= sc_hi;
        }

        // --- AV ---
#pragma unroll
        for (int kk = 0; kk < 4; kk++) {
            uint32_t pa0 = pack_bf16x2(sacc[2 * kk][0],     sacc[2 * kk][1]);
            uint32_t pa1 = pack_bf16x2(sacc[2 * kk][2],     sacc[2 * kk][3]);
            uint32_t pa2 = pack_bf16x2(sacc[2 * kk + 1][0], sacc[2 * kk + 1][1]);
            uint32_t pa3 = pack_bf16x2(sacc[2 * kk + 1][2], sacc[2 * kk + 1][3]);
            uint32_t vrow_a = vs_base + kk * 16 * (VS_PITCH * 2);
#pragma unroll
            for (int vt = 0; vt < 16; vt++) {
                uint32_t d0, d1, d2, d3;
                ldsm_x4_trans(d0, d1, d2, d3, vrow_a + (wn * 256 + vt * 16) * 2);
                mma_bf16(acc[2 * vt][0], acc[2 * vt][1], acc[2 * vt][2], acc[2 * vt][3],
                         pa0, pa1, pa2, pa3, d0, d1);
                mma_bf16(acc[2 * vt + 1][0], acc[2 * vt + 1][1], acc[2 * vt + 1][2], acc[2 * vt + 1][3],
                         pa0, pa1, pa2, pa3, d2, d3);
            }
        }
        __syncthreads();   // all reads of buffer `cur` done before it is refilled
    }

    // --- epilogue: normalize, write bf16 av ---
    float inv_lo = 1.f / ls_lo, inv_hi = 1.f / ls_hi;
    int row_lo = qt * 64 + wm * 16 + (l >> 2);
    int col0   = wn * 256 + 2 * (l & 3);
    __nv_bfloat16* av_lo = g_avb + ((size_t)b * LL + row_lo) * CC;
    __nv_bfloat16* av_hi = av_lo + 8 * CC;
#pragma unroll
    for (int nt = 0; nt < 32; nt++) {
        int c = col0 + nt * 8;
        *(uint32_t*)(av_lo + c) = pack_bf16x2(acc[nt][0] * inv_lo, acc[nt][1] * inv_lo);
        *(uint32_t*)(av_hi + c) = pack_bf16x2(acc[nt][2] * inv_hi, acc[nt][3] * inv_hi);
    }
}

// ---------------- kernel 3: output projection (bf16 HMMA) + residual -------
__global__ __launch_bounds__(256) void out_kernel(const float* __restrict__ x,
                                                  const float* __restrict__ bo,
                                                  const float* __restrict__ gamma,
                                                  float* __restrict__ out) {
    int b  = blockIdx.z;
    int ot = blockIdx.y;   // 0..3
    int lt = blockIdx.x;   // 0..15
    int t  = threadIdx.x;
    int w  = t >> 5, ln = t & 31;
    int wm = w & 3;
    int wn = w >> 2;

    __shared__ __align__(16) __nv_bfloat16 As_[128 * WS_PITCH];
    __shared__ __align__(16) __nv_bfloat16 Bs_[128 * WS_PITCH];

    float acc[2][8][4];
#pragma unroll
    for (int mt = 0; mt < 2; mt++)
#pragma unroll
        for (int nt = 0; nt < 8; nt++)
#pragma unroll
            for (int i = 0; i < 4; i++) acc[mt][nt][i] = 0.f;

    int o0 = ot * 128;
    uint32_t ab = (uint32_t)__cvta_generic_to_shared(As_)
                + (uint32_t)(((ln & 7) + 8 * ((ln >> 3) & 1)) * (WS_PITCH * 2))
                + 16 * ((ln >> 4) & 1) + (uint32_t)(wm * 32 * (WS_PITCH * 2));
    uint32_t bb = (uint32_t)__cvta_generic_to_shared(Bs_)
                + (uint32_t)(((ln & 7) + 8 * ((ln >> 4) & 1)) * (WS_PITCH * 2))
                + 16 * ((ln >> 3) & 1) + (uint32_t)(wn * 64 * (WS_PITCH * 2));

    for (int k0 = 0; k0 < CC; k0 += 64) {
        __syncthreads();
        {
            const uint4* ag = (const uint4*)(g_wob + (size_t)o0 * CC + k0);
            const uint4* bg = (const uint4*)(g_avb + ((size_t)b * LL + lt * 128) * CC + k0);
#pragma unroll
            for (int i = 0; i < 4; i++) {
                int e = t + 256 * i;
                int row = e >> 3, c = e & 7;
                *(uint4*)(As_ + row * WS_PITCH + c * 8) = ag[row * 64 + c];
                *(uint4*)(Bs_ + row * WS_PITCH + c * 8) = bg[row * 64 + c];
            }
        }
        __syncthreads();
#pragma unroll
        for (int kk = 0; kk < 4; kk++) {
            uint32_t a[2][4];
#pragma unroll
            for (int mt = 0; mt < 2; mt++)
                ldsm_x4(a[mt][0], a[mt][1], a[mt][2], a[mt][3],
                        ab + mt * 16 * (WS_PITCH * 2) + kk * 32);
#pragma unroll
            for (int ntp = 0; ntp < 4; ntp++) {
                uint32_t b0, b1, b2, b3;
                ldsm_x4(b0, b1, b2, b3, bb + ntp * 16 * (WS_PITCH * 2) + kk * 32);
#pragma unroll
                for (int mt = 0; mt < 2; mt++) {
                    mma_bf16(acc[mt][2 * ntp][0], acc[mt][2 * ntp][1],
                             acc[mt][2 * ntp][2], acc[mt][2 * ntp][3],
                             a[mt][0], a[mt][1], a[mt][2], a[mt][3], b0, b1);
                    mma_bf16(acc[mt][2 * ntp + 1][0], acc[mt][2 * ntp + 1][1],
                             acc[mt][2 * ntp + 1][2], acc[mt][2 * ntp + 1][3],
                             a[mt][0], a[mt][1], a[mt][2], a[mt][3], b2, b3);
                }
            }
        }
    }

    float g = gamma[0];
    int cl = 2 * (ln & 3);
#pragma unroll
    for (int mt = 0; mt < 2; mt++) {
        int o_r = o0 + wm * 32 + mt * 16 + (ln >> 2);
        float b0v = bo[o_r], b1v = bo[o_r + 8];
#pragma unroll
        for (int nt = 0; nt < 8; nt++) {
            int lc = lt * 128 + wn * 64 + nt * 8 + cl;
            size_t base0 = ((size_t)b * CC + o_r) * LL + lc;
            size_t base1 = base0 + (size_t)8 * LL;
            float2 xv0 = *(const float2*)(x + base0);
            float2 xv1 = *(const float2*)(x + base1);
            float2 r0, r1;
            r0.x = g * (acc[mt][nt][0] + b0v) + xv0.x;
            r0.y = g * (acc[mt][nt][1] + b0v) + xv0.y;
            r1.x = g * (acc[mt][nt][2] + b1v) + xv1.x;
            r1.y = g * (acc[mt][nt][3] + b1v) + xv1.y;
            *(float2*)(out + base0) = r0;
            *(float2*)(out + base1) = r1;
        }
    }
}

// ---------------- launch ----------------------------------------------------
extern "C" void kernel_launch(void* const* d_in, const int* in_sizes, int n_in,
                              void* d_out, int out_size) {
    const float* x     = (const float*)d_in[0];
    const float* wq    = (const float*)d_in[1];
    const float* bq    = (const float*)d_in[2];
    const float* wk    = (const float*)d_in[3];
    const float* bk    = (const float*)d_in[4];
    const float* wv    = (const float*)d_in[5];
    const float* bv    = (const float*)d_in[6];
    const float* wo    = (const float*)d_in[7];
    const float* bo    = (const float*)d_in[8];
    const float* gamma = (const float*)d_in[9];
    float* out = (float*)d_out;

    cudaFuncSetAttribute(attn_kernel, cudaFuncAttributeMaxDynamicSharedMemorySize,
                         SM_ATTN_BYTES);

    prep_kernel<<<(CC * CC + 255) / 256 + 256, 256>>>(wq, bq, wk, bk, wv, bv, wo);
    xconv_kernel<<<((size_t)BB * CC * LL / 4) / 256, 256>>>(x);

    dim3 g1(LL / 128, MQKV / 128, BB);
    qkv_kernel<<<g1, 256>>>();

    dim3 g2(LL / 64, BB);
    attn_kernel<<<g2, 256, SM_ATTN_BYTES>>>();

    dim3 g3(LL / 128, CC / 128, BB);
    out_kernel<<<g3, 256>>>(x, bo, gamma, out);
}

// round 8
// speedup vs baseline: 12.2043x; 1.0597x over previous
#include <cuda_runtime.h>
#include <cuda_bf16.h>
#include <cstdint>

// Problem constants
#define BB   16
#define CC   512
#define LL   2048
#define DQK  64
#define MQKV 640   // 64 q + 64 k + 512 v output channels

// ---------------- scratch (device globals; no dynamic allocation) ----------
__device__ float g_bias[MQKV];
__device__ __nv_bfloat16 g_wb[MQKV * CC];               // [o][c] bf16 qkv weights
__device__ __nv_bfloat16 g_wob[CC * CC];                // [o][c] bf16 wo
__device__ __nv_bfloat16 g_xb[(size_t)BB * CC * LL];    // [b][c][l] bf16
__device__ __nv_bfloat16 g_qb[(size_t)BB * LL * DQK];   // [b][l][d]
__device__ __nv_bfloat16 g_kb[(size_t)BB * LL * DQK];   // [b][l][d]
__device__ __nv_bfloat16 g_vb[(size_t)BB * LL * CC];    // [b][l][c]
__device__ __nv_bfloat16 g_avb[(size_t)BB * LL * CC];   // [b][l][c]

// ---------------- helpers ---------------------------------------------------
__device__ __forceinline__ uint32_t pack_bf16x2(float lo, float hi) {
    uint32_t r;
    asm volatile("cvt.rn.bf16x2.f32 %0, %1, %2;" : "=r"(r) : "f"(hi), "f"(lo));
    return r;
}
__device__ __forceinline__ void ldsm_x4(uint32_t& d0, uint32_t& d1, uint32_t& d2,
                                        uint32_t& d3, uint32_t addr) {
    asm volatile("ldmatrix.sync.aligned.m8n8.x4.shared.b16 {%0,%1,%2,%3}, [%4];"
                 : "=r"(d0), "=r"(d1), "=r"(d2), "=r"(d3) : "r"(addr));
}
__device__ __forceinline__ void ldsm_x4_trans(uint32_t& d0, uint32_t& d1, uint32_t& d2,
                                              uint32_t& d3, uint32_t addr) {
    asm volatile("ldmatrix.sync.aligned.m8n8.x4.trans.shared.b16 {%0,%1,%2,%3}, [%4];"
                 : "=r"(d0), "=r"(d1), "=r"(d2), "=r"(d3) : "r"(addr));
}
__device__ __forceinline__ void mma_bf16(float& c0, float& c1, float& c2, float& c3,
                                         uint32_t a0, uint32_t a1, uint32_t a2, uint32_t a3,
                                         uint32_t b0, uint32_t b1) {
    asm volatile("mma.sync.aligned.m16n8k16.row.col.f32.bf16.bf16.f32 "
                 "{%0,%1,%2,%3}, {%4,%5,%6,%7}, {%8,%9}, {%0,%1,%2,%3};"
                 : "+f"(c0), "+f"(c1), "+f"(c2), "+f"(c3)
                 : "r"(a0), "r"(a1), "r"(a2), "r"(a3), "r"(b0), "r"(b1));
}
__device__ __forceinline__ void cp_async16(uint32_t smem_addr, const void* gptr) {
    asm volatile("cp.async.cg.shared.global [%0], [%1], 16;"
                 :: "r"(smem_addr), "l"(gptr));
}
__device__ __forceinline__ void cp_commit() {
    asm volatile("cp.async.commit_group;");
}
template <int N> __device__ __forceinline__ void cp_wait() {
    asm volatile("cp.async.wait_group %0;" :: "n"(N));
}

// ---------------- kernel 0a: weights -> bf16, bias concat -------------------
__global__ void prep_kernel(const float* __restrict__ wq, const float* __restrict__ bq,
                            const float* __restrict__ wk, const float* __restrict__ bk,
                            const float* __restrict__ wv, const float* __restrict__ bv,
                            const float* __restrict__ wo) {
    int idx = blockIdx.x * blockDim.x + threadIdx.x;
    if (idx < MQKV * CC) {
        int row = idx >> 9;
        int c   = idx & 511;
        float val;
        if (row < 64)        val = wq[row * CC + c];
        else if (row < 128)  val = wk[(row - 64) * CC + c];
        else                 val = wv[(row - 128) * CC + c];
        g_wb[idx] = __float2bfloat16(val);
    }
    if (idx < CC * CC) g_wob[idx] = __float2bfloat16(wo[idx]);
    if (idx < MQKV) {
        float bv_;
        if (idx < 64)        bv_ = bq[idx];
        else if (idx < 128)  bv_ = bk[idx - 64];
        else                 bv_ = bv[idx - 128];
        g_bias[idx] = bv_;
    }
}

// ---------------- kernel 0b: x -> bf16 --------------------------------------
__global__ __launch_bounds__(256) void xconv_kernel(const float* __restrict__ x) {
    size_t i = (size_t)blockIdx.x * 256 + threadIdx.x;   // float4 index
    float4 v = ((const float4*)x)[i];
    uint2 pk;
    pk.x = pack_bf16x2(v.x, v.y);
    pk.y = pack_bf16x2(v.z, v.w);
    *(uint2*)(g_xb + 4 * i) = pk;
}

// ---------------- kernel 1: QKV projection (bf16 HMMA) ----------------------
// C[l, o] = sum_c X[c,l] * W[o,c]; block 128 l x 128 o, k-chunks of 64.
#define XS_PITCH 136
#define WS_PITCH 72
__global__ __launch_bounds__(256) void qkv_kernel() {
    int b  = blockIdx.z;
    int ot = blockIdx.y;   // 0..4
    int lt = blockIdx.x;   // 0..15
    int t  = threadIdx.x;
    int w  = t >> 5, ln = t & 31;
    int wm = w & 3;
    int wn = w >> 2;

    __shared__ __align__(16) __nv_bfloat16 Xs[64 * XS_PITCH];
    __shared__ __align__(16) __nv_bfloat16 Ws[128 * WS_PITCH];

    float acc[2][8][4];
#pragma unroll
    for (int mt = 0; mt < 2; mt++)
#pragma unroll
        for (int nt = 0; nt < 8; nt++)
#pragma unroll
            for (int i = 0; i < 4; i++) acc[mt][nt][i] = 0.f;

    int o0 = ot * 128;
    uint32_t xa_base = (uint32_t)__cvta_generic_to_shared(Xs)
                     + (uint32_t)(((ln & 7) + 8 * ((ln >> 3) & 1)) * (XS_PITCH * 2))
                     + 16 * ((ln >> 4) & 1) + (uint32_t)(wm * 32 * 2);
    uint32_t ws_base = (uint32_t)__cvta_generic_to_shared(Ws)
                     + (uint32_t)(((ln & 7) + 8 * ((ln >> 4) & 1)) * (WS_PITCH * 2))
                     + 16 * ((ln >> 3) & 1) + (uint32_t)(wn * 64 * (WS_PITCH * 2));

    for (int k0 = 0; k0 < CC; k0 += 64) {
        __syncthreads();
        {
            const uint4* xg = (const uint4*)(g_xb + ((size_t)b * CC + k0) * LL + lt * 128);
#pragma unroll
            for (int i = 0; i < 4; i++) {
                int e = t + 256 * i;
                int row = e >> 4, c = e & 15;
                *(uint4*)(Xs + row * XS_PITCH + c * 8) = xg[row * 256 + c];
            }
            const uint4* wg = (const uint4*)(g_wb + (size_t)o0 * CC + k0);
#pragma unroll
            for (int i = 0; i < 4; i++) {
                int e = t + 256 * i;
                int row = e >> 3, c = e & 7;
                *(uint4*)(Ws + row * WS_PITCH + c * 8) = wg[row * 64 + c];
            }
        }
        __syncthreads();
#pragma unroll
        for (int kk = 0; kk < 4; kk++) {
            uint32_t ta[2][4];
#pragma unroll
            for (int mt = 0; mt < 2; mt++)
                ldsm_x4_trans(ta[mt][0], ta[mt][1], ta[mt][2], ta[mt][3],
                              xa_base + kk * 16 * (XS_PITCH * 2) + mt * 16 * 2);
#pragma unroll
            for (int ntp = 0; ntp < 4; ntp++) {
                uint32_t b0, b1, b2, b3;
                ldsm_x4(b0, b1, b2, b3, ws_base + ntp * 16 * (WS_PITCH * 2) + kk * 32);
#pragma unroll
                for (int mt = 0; mt < 2; mt++) {
                    mma_bf16(acc[mt][2 * ntp][0], acc[mt][2 * ntp][1],
                             acc[mt][2 * ntp][2], acc[mt][2 * ntp][3],
                             ta[mt][0], ta[mt][2], ta[mt][1], ta[mt][3], b0, b1);
                    mma_bf16(acc[mt][2 * ntp + 1][0], acc[mt][2 * ntp + 1][1],
                             acc[mt][2 * ntp + 1][2], acc[mt][2 * ntp + 1][3],
                             ta[mt][0], ta[mt][2], ta[mt][1], ta[mt][3], b2, b3);
                }
            }
        }
    }

    int og0 = o0 + wn * 64;
    __nv_bfloat16* dst;
    int dstride, doff;
    if (og0 == 0)       { dst = g_qb + (size_t)b * LL * DQK; dstride = DQK; doff = 0; }
    else if (og0 == 64) { dst = g_kb + (size_t)b * LL * DQK; dstride = DQK; doff = 0; }
    else                { dst = g_vb + (size_t)b * LL * CC;  dstride = CC;  doff = og0 - 128; }

    int cl = 2 * (ln & 3);
    float bias_lo[8], bias_hi[8];
#pragma unroll
    for (int nt = 0; nt < 8; nt++) {
        bias_lo[nt] = g_bias[og0 + nt * 8 + cl];
        bias_hi[nt] = g_bias[og0 + nt * 8 + cl + 1];
    }
#pragma unroll
    for (int mt = 0; mt < 2; mt++) {
        int row = lt * 128 + wm * 32 + mt * 16 + (ln >> 2);
#pragma unroll
        for (int nt = 0; nt < 8; nt++) {
            uint32_t p0 = pack_bf16x2(acc[mt][nt][0] + bias_lo[nt],
                                      acc[mt][nt][1] + bias_hi[nt]);
            uint32_t p1 = pack_bf16x2(acc[mt][nt][2] + bias_lo[nt],
                                      acc[mt][nt][3] + bias_hi[nt]);
            *(uint32_t*)(dst + (size_t)row * dstride + doff + nt * 8 + cl) = p0;
            *(uint32_t*)(dst + (size_t)(row + 8) * dstride + doff + nt * 8 + cl) = p1;
        }
    }
}

// ---------------- kernel 2: flash attention (bf16 HMMA, cp.async, split) ----
// Grid: (qt=32, ch=2, b=16). CTA: 64 queries x 256 channels, 8 warps.
// Constant-shift softmax: p = exp(s - 8); shift cancels in normalization.
#define QS_PITCH 72      // bf16; 144B rows
#define VS2_PITCH 264    // bf16; 528B rows -> trans-ldmatrix conflict-free
#define SMO_QS  0
#define SMO_KS0 (64 * QS_PITCH)
#define SMO_KS1 (SMO_KS0 + 64 * QS_PITCH)
#define SMO_VS0 (SMO_KS1 + 64 * QS_PITCH)
#define SMO_VS1 (SMO_VS0 + 64 * VS2_PITCH)
#define SM_ATTN_BF16 (SMO_VS1 + 64 * VS2_PITCH)
#define SM_ATTN_BYTES (SM_ATTN_BF16 * 2)

__global__ __launch_bounds__(256, 2) void attn_kernel() {
    extern __shared__ __align__(16) __nv_bfloat16 sm[];
    uint32_t smem_u32 = (uint32_t)__cvta_generic_to_shared(sm);

    int b  = blockIdx.z;
    int ch = blockIdx.y;        // channel half: 0 or 1
    int qt = blockIdx.x;
    int t  = threadIdx.x;
    int w  = t >> 5, l = t & 31;
    int wm = w & 3;             // row group (16 rows)
    int wn = w >> 2;            // 128-channel half within this CTA's 256

    const char* kg_base = (const char*)(g_kb + (size_t)b * LL * DQK);
    const char* vg_base = (const char*)(g_vb + (size_t)b * LL * CC) + ch * 256 * 2;

    int krow = t >> 3, kcol = t & 7;       // K: 64 rows x 8 chunks (2 iters)
    int vrow = t >> 5, vcol = t & 31;      // V: 64 rows x 32 chunks (8 iters)

    auto issue_tile = [&](int kb, int bf) {
        const char* kg = kg_base + (size_t)kb * 64 * DQK * 2;
        uint32_t ks = smem_u32 + (bf ? SMO_KS1 : SMO_KS0) * 2;
#pragma unroll
        for (int i = 0; i < 2; i++) {
            int row = krow + 32 * i;
            cp_async16(ks + row * (QS_PITCH * 2) + kcol * 16,
                       kg + row * (DQK * 2) + kcol * 16);
        }
        const char* vg = vg_base + (size_t)kb * 64 * CC * 2;
        uint32_t vs = smem_u32 + (bf ? SMO_VS1 : SMO_VS0) * 2;
#pragma unroll
        for (int i = 0; i < 8; i++) {
            int row = vrow + 8 * i;
            cp_async16(vs + row * (VS2_PITCH * 2) + vcol * 16,
                       vg + row * (CC * 2) + vcol * 16);
        }
        cp_commit();
    };

    // --- load Q tile [64][64] -> Qs ---
    {
        const uint4* qg = (const uint4*)(g_qb + ((size_t)b * LL + qt * 64) * DQK);
        __nv_bfloat16* Qs = sm + SMO_QS;
#pragma unroll
        for (int i = 0; i < 2; i++) {
            int e = t + 256 * i;
            int row = e >> 3, c = e & 7;
            *(uint4*)(Qs + row * QS_PITCH + c * 8) = qg[row * 8 + c];
        }
    }
    issue_tile(0, 0);
    __syncthreads();

    uint32_t qa[4][4];
    {
        uint32_t base = smem_u32 + SMO_QS * 2
                      + (uint32_t)((wm * 16 + (l & 7) + 8 * ((l >> 3) & 1)) * (QS_PITCH * 2))
                      + 16 * ((l >> 4) & 1);
#pragma unroll
        for (int kk = 0; kk < 4; kk++)
            ldsm_x4(qa[kk][0], qa[kk][1], qa[kk][2], qa[kk][3], base + kk * 32);
    }

    uint32_t ks_lane = (uint32_t)(((l & 7) + 8 * ((l >> 4) & 1)) * (QS_PITCH * 2))
                     + 16 * ((l >> 3) & 1);
    uint32_t vs_lane = (uint32_t)(((l & 7) + 8 * ((l >> 3) & 1)) * (VS2_PITCH * 2))
                     + 16 * ((l >> 4) & 1);
    uint32_t ks_b[2] = { smem_u32 + SMO_KS0 * 2 + ks_lane, smem_u32 + SMO_KS1 * 2 + ks_lane };
    uint32_t vs_b[2] = { smem_u32 + SMO_VS0 * 2 + vs_lane, smem_u32 + SMO_VS1 * 2 + vs_lane };

    float ls_lo = 0.f, ls_hi = 0.f;
    float acc[16][4];
#pragma unroll
    for (int n = 0; n < 16; n++)
#pragma unroll
        for (int i = 0; i < 4; i++) acc[n][i] = 0.f;

    for (int kb = 0; kb < 32; kb++) {
        int cur = kb & 1;
        if (kb + 1 < 32) issue_tile(kb + 1, cur ^ 1);
        else             cp_commit();
        cp_wait<1>();
        __syncthreads();

        uint32_t ks_base = ks_b[cur];
        uint32_t vs_base = vs_b[cur];

        // --- S = Q K^T ---
        float sacc[8][4];
#pragma unroll
        for (int nt = 0; nt < 8; nt++)
#pragma unroll
            for (int i = 0; i < 4; i++) sacc[nt][i] = 0.f;

#pragma unroll
        for (int kk = 0; kk < 4; kk++) {
#pragma unroll
            for (int ntp = 0; ntp < 4; ntp++) {
                uint32_t d0, d1, d2, d3;
                ldsm_x4(d0, d1, d2, d3, ks_base + ntp * 16 * (QS_PITCH * 2) + kk * 32);
                mma_bf16(sacc[2 * ntp][0], sacc[2 * ntp][1], sacc[2 * ntp][2], sacc[2 * ntp][3],
                         qa[kk][0], qa[kk][1], qa[kk][2], qa[kk][3], d0, d1);
                mma_bf16(sacc[2 * ntp + 1][0], sacc[2 * ntp + 1][1], sacc[2 * ntp + 1][2], sacc[2 * ntp + 1][3],
                         qa[kk][0], qa[kk][1], qa[kk][2], qa[kk][3], d2, d3);
            }
        }

        // --- constant-shift exp; accumulate per-thread partial sums ---
#pragma unroll
        for (int nt = 0; nt < 8; nt++) {
            sacc[nt][0] = __expf(sacc[nt][0] - 8.f);
            sacc[nt][1] = __expf(sacc[nt][1] - 8.f);
            sacc[nt][2] = __expf(sacc[nt][2] - 8.f);
            sacc[nt][3] = __expf(sacc[nt][3] - 8.f);
            ls_lo += sacc[nt][0] + sacc[nt][1];
            ls_hi += sacc[nt][2] + sacc[nt][3];
        }

        // --- AV: P x V (this CTA's 256 channels; warp handles 128) ---
#pragma unroll
        for (int kk = 0; kk < 4; kk++) {
            uint32_t pa0 = pack_bf16x2(sacc[2 * kk][0],     sacc[2 * kk][1]);
            uint32_t pa1 = pack_bf16x2(sacc[2 * kk][2],     sacc[2 * kk][3]);
            uint32_t pa2 = pack_bf16x2(sacc[2 * kk + 1][0], sacc[2 * kk + 1][1]);
            uint32_t pa3 = pack_bf16x2(sacc[2 * kk + 1][2], sacc[2 * kk + 1][3]);
            uint32_t vrow_a = vs_base + kk * 16 * (VS2_PITCH * 2);
#pragma unroll
            for (int vt = 0; vt < 8; vt++) {
                uint32_t d0, d1, d2, d3;
                ldsm_x4_trans(d0, d1, d2, d3, vrow_a + (wn * 128 + vt * 16) * 2);
                mma_bf16(acc[2 * vt][0], acc[2 * vt][1], acc[2 * vt][2], acc[2 * vt][3],
                         pa0, pa1, pa2, pa3, d0, d1);
                mma_bf16(acc[2 * vt + 1][0], acc[2 * vt + 1][1], acc[2 * vt + 1][2], acc[2 * vt + 1][3],
                         pa0, pa1, pa2, pa3, d2, d3);
            }
        }
        __syncthreads();   // reads of buffer `cur` done before refill
    }

    // --- epilogue: quad-reduce row sums once, normalize, write bf16 av ---
    ls_lo += __shfl_xor_sync(0xffffffffu, ls_lo, 1);
    ls_lo += __shfl_xor_sync(0xffffffffu, ls_lo, 2);
    ls_hi += __shfl_xor_sync(0xffffffffu, ls_hi, 1);
    ls_hi += __shfl_xor_sync(0xffffffffu, ls_hi, 2);
    float inv_lo = 1.f / ls_lo, inv_hi = 1.f / ls_hi;

    int row_lo = qt * 64 + wm * 16 + (l >> 2);
    int col0   = ch * 256 + wn * 128 + 2 * (l & 3);
    __nv_bfloat16* av_lo = g_avb + ((size_t)b * LL + row_lo) * CC;
    __nv_bfloat16* av_hi = av_lo + 8 * CC;
#pragma unroll
    for (int nt = 0; nt < 16; nt++) {
        int c = col0 + nt * 8;
        *(uint32_t*)(av_lo + c) = pack_bf16x2(acc[nt][0] * inv_lo, acc[nt][1] * inv_lo);
        *(uint32_t*)(av_hi + c) = pack_bf16x2(acc[nt][2] * inv_hi, acc[nt][3] * inv_hi);
    }
}

// ---------------- kernel 3: output projection (bf16 HMMA) + residual -------
__global__ __launch_bounds__(256) void out_kernel(const float* __restrict__ x,
                                                  const float* __restrict__ bo,
                                                  const float* __restrict__ gamma,
                                                  float* __restrict__ out) {
    int b  = blockIdx.z;
    int ot = blockIdx.y;   // 0..3
    int lt = blockIdx.x;   // 0..15
    int t  = threadIdx.x;
    int w  = t >> 5, ln = t & 31;
    int wm = w & 3;
    int wn = w >> 2;

    __shared__ __align__(16) __nv_bfloat16 As_[128 * WS_PITCH];
    __shared__ __align__(16) __nv_bfloat16 Bs_[128 * WS_PITCH];

    float acc[2][8][4];
#pragma unroll
    for (int mt = 0; mt < 2; mt++)
#pragma unroll
        for (int nt = 0; nt < 8; nt++)
#pragma unroll
            for (int i = 0; i < 4; i++) acc[mt][nt][i] = 0.f;

    int o0 = ot * 128;
    uint32_t ab = (uint32_t)__cvta_generic_to_shared(As_)
                + (uint32_t)(((ln & 7) + 8 * ((ln >> 3) & 1)) * (WS_PITCH * 2))
                + 16 * ((ln >> 4) & 1) + (uint32_t)(wm * 32 * (WS_PITCH * 2));
    uint32_t bb = (uint32_t)__cvta_generic_to_shared(Bs_)
                + (uint32_t)(((ln & 7) + 8 * ((ln >> 4) & 1)) * (WS_PITCH * 2))
                + 16 * ((ln >> 3) & 1) + (uint32_t)(wn * 64 * (WS_PITCH * 2));

    for (int k0 = 0; k0 < CC; k0 += 64) {
        __syncthreads();
        {
            const uint4* ag = (const uint4*)(g_wob + (size_t)o0 * CC + k0);
            const uint4* bg = (const uint4*)(g_avb + ((size_t)b * LL + lt * 128) * CC + k0);
#pragma unroll
            for (int i = 0; i < 4; i++) {
                int e = t + 256 * i;
                int row = e >> 3, c = e & 7;
                *(uint4*)(As_ + row * WS_PITCH + c * 8) = ag[row * 64 + c];
                *(uint4*)(Bs_ + row * WS_PITCH + c * 8) = bg[row * 64 + c];
            }
        }
        __syncthreads();
#pragma unroll
        for (int kk = 0; kk < 4; kk++) {
            uint32_t a[2][4];
#pragma unroll
            for (int mt = 0; mt < 2; mt++)
                ldsm_x4(a[mt][0], a[mt][1], a[mt][2], a[mt][3],
                        ab + mt * 16 * (WS_PITCH * 2) + kk * 32);
#pragma unroll
            for (int ntp = 0; ntp < 4; ntp++) {
                uint32_t b0, b1, b2, b3;
                ldsm_x4(b0, b1, b2, b3, bb + ntp * 16 * (WS_PITCH * 2) + kk * 32);
#pragma unroll
                for (int mt = 0; mt < 2; mt++) {
                    mma_bf16(acc[mt][2 * ntp][0], acc[mt][2 * ntp][1],
                             acc[mt][2 * ntp][2], acc[mt][2 * ntp][3],
                             a[mt][0], a[mt][1], a[mt][2], a[mt][3], b0, b1);
                    mma_bf16(acc[mt][2 * ntp + 1][0], acc[mt][2 * ntp + 1][1],
                             acc[mt][2 * ntp + 1][2], acc[mt][2 * ntp + 1][3],
                             a[mt][0], a[mt][1], a[mt][2], a[mt][3], b2, b3);
                }
            }
        }
    }

    float g = gamma[0];
    int cl = 2 * (ln & 3);
#pragma unroll
    for (int mt = 0; mt < 2; mt++) {
        int o_r = o0 + wm * 32 + mt * 16 + (ln >> 2);
        float b0v = bo[o_r], b1v = bo[o_r + 8];
#pragma unroll
        for (int nt = 0; nt < 8; nt++) {
            int lc = lt * 128 + wn * 64 + nt * 8 + cl;
            size_t base0 = ((size_t)b * CC + o_r) * LL + lc;
            size_t base1 = base0 + (size_t)8 * LL;
            float2 xv0 = *(const float2*)(x + base0);
            float2 xv1 = *(const float2*)(x + base1);
            float2 r0, r1;
            r0.x = g * (acc[mt][nt][0] + b0v) + xv0.x;
            r0.y = g * (acc[mt][nt][1] + b0v) + xv0.y;
            r1.x = g * (acc[mt][nt][2] + b1v) + xv1.x;
            r1.y = g * (acc[mt][nt][3] + b1v) + xv1.y;
            *(float2*)(out + base0) = r0;
            *(float2*)(out + base1) = r1;
        }
    }
}

// ---------------- launch ----------------------------------------------------
extern "C" void kernel_launch(void* const* d_in, const int* in_sizes, int n_in,
                              void* d_out, int out_size) {
    const float* x     = (const float*)d_in[0];
    const float* wq    = (const float*)d_in[1];
    const float* bq    = (const float*)d_in[2];
    const float* wk    = (const float*)d_in[3];
    const float* bk    = (const float*)d_in[4];
    const float* wv    = (const float*)d_in[5];
    const float* bv    = (const float*)d_in[6];
    const float* wo    = (const float*)d_in[7];
    const float* bo    = (const float*)d_in[8];
    const float* gamma = (const float*)d_in[9];
    float* out = (float*)d_out;

    cudaFuncSetAttribute(attn_kernel, cudaFuncAttributeMaxDynamicSharedMemorySize,
                         SM_ATTN_BYTES);

    prep_kernel<<<(CC * CC + 255) / 256 + 256, 256>>>(wq, bq, wk, bk, wv, bv, wo);
    xconv_kernel<<<((size_t)BB * CC * LL / 4) / 256, 256>>>(x);

    dim3 g1(LL / 128, MQKV / 128, BB);
    qkv_kernel<<<g1, 256>>>();

    dim3 g2(LL / 64, 2, BB);
    attn_kernel<<<g2, 256, SM_ATTN_BYTES>>>();

    dim3 g3(LL / 128, CC / 128, BB);
    out_kernel<<<g3, 256>>>(x, bo, gamma, out);
}

// round 10
// speedup vs baseline: 12.9538x; 1.0614x over previous
#include <cuda_runtime.h>
#include <cuda_bf16.h>
#include <cstdint>

// Problem constants
#define BB   16
#define CC   512
#define LL   2048
#define DQK  64
#define MQKV 640
#define NKB  32

// ---------------- scratch (device globals) ----------------------------------
__device__ float g_bias[MQKV];
__device__ __nv_bfloat16 g_wb[MQKV * CC];               // [o][c]
__device__ __nv_bfloat16 g_wob[CC * CC];                // [o][c]
__device__ __nv_bfloat16 g_xb[(size_t)BB * CC * LL];    // [b][c][l]
__device__ __nv_bfloat16 g_qb[(size_t)BB * LL * DQK];   // [b][l][d]
__device__ __nv_bfloat16 g_kb[(size_t)BB * LL * DQK];   // [b][l][d]
__device__ __nv_bfloat16 g_vb[(size_t)BB * LL * CC];    // [b][l][c]
__device__ __nv_bfloat16 g_avb[(size_t)BB * LL * CC];   // [b][l][c]

// ---------------- helpers ----------------------------------------------------
__device__ __forceinline__ uint32_t pack_bf16x2(float lo, float hi) {
    uint32_t r;
    asm volatile("cvt.rn.bf16x2.f32 %0, %1, %2;" : "=r"(r) : "f"(hi), "f"(lo));
    return r;
}
__device__ __forceinline__ void ldsm_x4(uint32_t& d0, uint32_t& d1, uint32_t& d2,
                                        uint32_t& d3, uint32_t addr) {
    asm volatile("ldmatrix.sync.aligned.m8n8.x4.shared.b16 {%0,%1,%2,%3}, [%4];"
                 : "=r"(d0), "=r"(d1), "=r"(d2), "=r"(d3) : "r"(addr));
}
__device__ __forceinline__ void ldsm_x4_trans(uint32_t& d0, uint32_t& d1, uint32_t& d2,
                                              uint32_t& d3, uint32_t addr) {
    asm volatile("ldmatrix.sync.aligned.m8n8.x4.trans.shared.b16 {%0,%1,%2,%3}, [%4];"
                 : "=r"(d0), "=r"(d1), "=r"(d2), "=r"(d3) : "r"(addr));
}
__device__ __forceinline__ void mma_bf16(float& c0, float& c1, float& c2, float& c3,
                                         uint32_t a0, uint32_t a1, uint32_t a2, uint32_t a3,
                                         uint32_t b0, uint32_t b1) {
    asm volatile("mma.sync.aligned.m16n8k16.row.col.f32.bf16.bf16.f32 "
                 "{%0,%1,%2,%3}, {%4,%5,%6,%7}, {%8,%9}, {%0,%1,%2,%3};"
                 : "+f"(c0), "+f"(c1), "+f"(c2), "+f"(c3)
                 : "r"(a0), "r"(a1), "r"(a2), "r"(a3), "r"(b0), "r"(b1));
}
__device__ __forceinline__ void cp_async16(uint32_t smem_addr, const void* gptr) {
    asm volatile("cp.async.cg.shared.global [%0], [%1], 16;"
                 :: "r"(smem_addr), "l"(gptr));
}
__device__ __forceinline__ void cp_commit() { asm volatile("cp.async.commit_group;"); }
template <int N> __device__ __forceinline__ void cp_wait() {
    asm volatile("cp.async.wait_group %0;" :: "n"(N));
}

// ---------------- kernel 0a: weights -> bf16, bias concat -------------------
__global__ void prep_kernel(const float* __restrict__ wq, const float* __restrict__ bq,
                            const float* __restrict__ wk, const float* __restrict__ bk,
                            const float* __restrict__ wv, const float* __restrict__ bv,
                            const float* __restrict__ wo) {
    int idx = blockIdx.x * blockDim.x + threadIdx.x;
    if (idx < MQKV * CC) {
        int row = idx >> 9;
        int c   = idx & 511;
        float val;
        if (row < 64)        val = wq[row * CC + c];
        else if (row < 128)  val = wk[(row - 64) * CC + c];
        else                 val = wv[(row - 128) * CC + c];
        g_wb[idx] = __float2bfloat16(val);
    }
    if (idx < CC * CC) g_wob[idx] = __float2bfloat16(wo[idx]);
    if (idx < MQKV) {
        float bv_;
        if (idx < 64)        bv_ = bq[idx];
        else if (idx < 128)  bv_ = bk[idx - 64];
        else                 bv_ = bv[idx - 128];
        g_bias[idx] = bv_;
    }
}

// ---------------- kernel 0b: x -> bf16 --------------------------------------
__global__ __launch_bounds__(256) void xconv_kernel(const float* __restrict__ x) {
    size_t i = (size_t)blockIdx.x * 256 + threadIdx.x;
    float4 v = ((const float4*)x)[i];
    uint2 pk;
    pk.x = pack_bf16x2(v.x, v.y);
    pk.y = pack_bf16x2(v.z, v.w);
    *(uint2*)(g_xb + 4 * i) = pk;
}

// ---------------- kernel 1: QKV projection (bf16 HMMA, cp.async 2-stage) ----
// C[l, o] = sum_c X[c,l] * W[o,c]; block 128 l x 128 o, k-chunks of 64.
// Dynamic smem stage: X tile 64x136 bf16 (17408 B) + W tile 128x72 (18432 B).
#define XS_PITCH 136
#define WS_PITCH 72
#define QKV_STAGE (64 * XS_PITCH * 2 + 128 * WS_PITCH * 2)   // 35840
#define QKV_SMEM  (2 * QKV_STAGE)
__global__ __launch_bounds__(256) void qkv_kernel() {
    extern __shared__ __align__(16) char qsm[];
    uint32_t sbase = (uint32_t)__cvta_generic_to_shared(qsm);

    int b  = blockIdx.z;
    int ot = blockIdx.y;
    int lt = blockIdx.x;
    int t  = threadIdx.x;
    int w  = t >> 5, ln = t & 31;
    int wm = w & 3;
    int wn = w >> 2;
    int o0 = ot * 128;

    auto issue_stage = [&](int k0, int buf) {
        uint32_t xs = sbase + buf * QKV_STAGE;
        const char* xg = (const char*)(g_xb + ((size_t)b * CC + k0) * LL + lt * 128);
#pragma unroll
        for (int i = 0; i < 4; i++) {
            int e = t + 256 * i;
            int row = e >> 4, c = e & 15;
            cp_async16(xs + row * (XS_PITCH * 2) + c * 16,
                       xg + (size_t)row * (LL * 2) + c * 16);
        }
        uint32_t ws = sbase + buf * QKV_STAGE + 64 * XS_PITCH * 2;
        const char* wg = (const char*)(g_wb + (size_t)o0 * CC + k0);
#pragma unroll
        for (int i = 0; i < 4; i++) {
            int e = t + 256 * i;
            int row = e >> 3, c = e & 7;
            cp_async16(ws + row * (WS_PITCH * 2) + c * 16,
                       wg + (size_t)row * (CC * 2) + c * 16);
        }
        cp_commit();
    };

    float acc[2][8][4];
#pragma unroll
    for (int mt = 0; mt < 2; mt++)
#pragma unroll
        for (int nt = 0; nt < 8; nt++)
#pragma unroll
            for (int i = 0; i < 4; i++) acc[mt][nt][i] = 0.f;

    uint32_t xa_lane = (uint32_t)(((ln & 7) + 8 * ((ln >> 3) & 1)) * (XS_PITCH * 2))
                     + 16 * ((ln >> 4) & 1) + (uint32_t)(wm * 32 * 2);
    uint32_t ws_lane = (uint32_t)(64 * XS_PITCH * 2)
                     + (uint32_t)(((ln & 7) + 8 * ((ln >> 4) & 1)) * (WS_PITCH * 2))
                     + 16 * ((ln >> 3) & 1) + (uint32_t)(wn * 64 * (WS_PITCH * 2));

    issue_stage(0, 0);

    for (int k0 = 0; k0 < CC; k0 += 64) {
        int buf = (k0 >> 6) & 1;
        cp_wait<0>();
        __syncthreads();
        if (k0 + 64 < CC) issue_stage(k0 + 64, buf ^ 1);

        uint32_t xa_base = sbase + buf * QKV_STAGE + xa_lane;
        uint32_t ws_base = sbase + buf * QKV_STAGE + ws_lane;
#pragma unroll
        for (int kk = 0; kk < 4; kk++) {
            uint32_t ta[2][4];
#pragma unroll
            for (int mt = 0; mt < 2; mt++)
                ldsm_x4_trans(ta[mt][0], ta[mt][1], ta[mt][2], ta[mt][3],
                              xa_base + kk * 16 * (XS_PITCH * 2) + mt * 16 * 2);
#pragma unroll
            for (int ntp = 0; ntp < 4; ntp++) {
                uint32_t b0, b1, b2, b3;
                ldsm_x4(b0, b1, b2, b3, ws_base + ntp * 16 * (WS_PITCH * 2) + kk * 32);
#pragma unroll
                for (int mt = 0; mt < 2; mt++) {
                    mma_bf16(acc[mt][2 * ntp][0], acc[mt][2 * ntp][1],
                             acc[mt][2 * ntp][2], acc[mt][2 * ntp][3],
                             ta[mt][0], ta[mt][2], ta[mt][1], ta[mt][3], b0, b1);
                    mma_bf16(acc[mt][2 * ntp + 1][0], acc[mt][2 * ntp + 1][1],
                             acc[mt][2 * ntp + 1][2], acc[mt][2 * ntp + 1][3],
                             ta[mt][0], ta[mt][2], ta[mt][1], ta[mt][3], b2, b3);
                }
            }
        }
        __syncthreads();   // all reads of buf done before it is refilled next iter
    }

    int og0 = o0 + wn * 64;
    __nv_bfloat16* dst;
    int dstride, doff;
    if (og0 == 0)       { dst = g_qb + (size_t)b * LL * DQK; dstride = DQK; doff = 0; }
    else if (og0 == 64) { dst = g_kb + (size_t)b * LL * DQK; dstride = DQK; doff = 0; }
    else                { dst = g_vb + (size_t)b * LL * CC;  dstride = CC;  doff = og0 - 128; }

    int cl = 2 * (ln & 3);
    float bias_lo[8], bias_hi[8];
#pragma unroll
    for (int nt = 0; nt < 8; nt++) {
        bias_lo[nt] = g_bias[og0 + nt * 8 + cl];
        bias_hi[nt] = g_bias[og0 + nt * 8 + cl + 1];
    }
#pragma unroll
    for (int mt = 0; mt < 2; mt++) {
        int row = lt * 128 + wm * 32 + mt * 16 + (ln >> 2);
#pragma unroll
        for (int nt = 0; nt < 8; nt++) {
            uint32_t p0 = pack_bf16x2(acc[mt][nt][0] + bias_lo[nt],
                                      acc[mt][nt][1] + bias_hi[nt]);
            uint32_t p1 = pack_bf16x2(acc[mt][nt][2] + bias_lo[nt],
                                      acc[mt][nt][3] + bias_hi[nt]);
            *(uint32_t*)(dst + (size_t)row * dstride + doff + nt * 8 + cl) = p0;
            *(uint32_t*)(dst + (size_t)(row + 8) * dstride + doff + nt * 8 + cl) = p1;
        }
    }
}

// ---------------- kernel 2: flash attention (bf16 HMMA, cp.async, split) ----
// Grid: (qt=32, ch=2, b=16). CTA: 64 queries x 256 channels, 8 warps.
// Constant-shift softmax: p = exp(s - 8); shift cancels in normalization.
#define QS_PITCH 72
#define VS2_PITCH 264
#define SMO_QS  0
#define SMO_KS0 (64 * QS_PITCH)
#define SMO_KS1 (SMO_KS0 + 64 * QS_PITCH)
#define SMO_VS0 (SMO_KS1 + 64 * QS_PITCH)
#define SMO_VS1 (SMO_VS0 + 64 * VS2_PITCH)
#define SM_ATTN_BF16 (SMO_VS1 + 64 * VS2_PITCH)
#define SM_ATTN_BYTES (SM_ATTN_BF16 * 2)

__global__ __launch_bounds__(256, 2) void attn_kernel() {
    extern __shared__ __align__(16) __nv_bfloat16 sm[];
    uint32_t smem_u32 = (uint32_t)__cvta_generic_to_shared(sm);

    int b  = blockIdx.z;
    int ch = blockIdx.y;
    int qt = blockIdx.x;
    int t  = threadIdx.x;
    int w  = t >> 5, l = t & 31;
    int wm = w & 3;
    int wn = w >> 2;

    const char* kg_base = (const char*)(g_kb + (size_t)b * LL * DQK);
    const char* vg_base = (const char*)(g_vb + (size_t)b * LL * CC) + ch * 256 * 2;

    int krow = t >> 3, kcol = t & 7;
    int vrow = t >> 5, vcol = t & 31;

    auto issue_tile = [&](int kb, int bf) {
        const char* kg = kg_base + (size_t)kb * 64 * (DQK * 2);
        uint32_t ks = smem_u32 + (bf ? SMO_KS1 : SMO_KS0) * 2;
#pragma unroll
        for (int i = 0; i < 2; i++) {
            int row = krow + 32 * i;
            cp_async16(ks + row * (QS_PITCH * 2) + kcol * 16,
                       kg + row * (DQK * 2) + kcol * 16);
        }
        const char* vg = vg_base + (size_t)kb * 64 * (CC * 2);
        uint32_t vs = smem_u32 + (bf ? SMO_VS1 : SMO_VS0) * 2;
#pragma unroll
        for (int i = 0; i < 8; i++) {
            int row = vrow + 8 * i;
            cp_async16(vs + row * (VS2_PITCH * 2) + vcol * 16,
                       vg + (size_t)row * (CC * 2) + vcol * 16);
        }
        cp_commit();
    };

    // Q tile [64][64] -> Qs (plain stores)
    {
        const uint4* qg = (const uint4*)(g_qb + ((size_t)b * LL + qt * 64) * DQK);
        __nv_bfloat16* Qs = sm + SMO_QS;
#pragma unroll
        for (int i = 0; i < 2; i++) {
            int e = t + 256 * i;
            int row = e >> 3, c = e & 7;
            *(uint4*)(Qs + row * QS_PITCH + c * 8) = qg[row * 8 + c];
        }
    }
    issue_tile(0, 0);
    __syncthreads();

    uint32_t qa[4][4];
    {
        uint32_t base = smem_u32 + SMO_QS * 2
                      + (uint32_t)((wm * 16 + (l & 7) + 8 * ((l >> 3) & 1)) * (QS_PITCH * 2))
                      + 16 * ((l >> 4) & 1);
#pragma unroll
        for (int kk = 0; kk < 4; kk++)
            ldsm_x4(qa[kk][0], qa[kk][1], qa[kk][2], qa[kk][3], base + kk * 32);
    }

    uint32_t ks_lane = (uint32_t)(((l & 7) + 8 * ((l >> 4) & 1)) * (QS_PITCH * 2))
                     + 16 * ((l >> 3) & 1);
    uint32_t vs_lane = (uint32_t)(((l & 7) + 8 * ((l >> 3) & 1)) * (VS2_PITCH * 2))
                     + 16 * ((l >> 4) & 1);
    uint32_t ks_b[2] = { smem_u32 + SMO_KS0 * 2 + ks_lane, smem_u32 + SMO_KS1 * 2 + ks_lane };
    uint32_t vs_b[2] = { smem_u32 + SMO_VS0 * 2 + vs_lane, smem_u32 + SMO_VS1 * 2 + vs_lane };

    float ls_lo = 0.f, ls_hi = 0.f;
    float acc[16][4];
#pragma unroll
    for (int n = 0; n < 16; n++)
#pragma unroll
        for (int i = 0; i < 4; i++) acc[n][i] = 0.f;

    for (int kb = 0; kb < NKB; kb++) {
        int cur = kb & 1;
        cp_wait<0>();            // tile kb resident
        __syncthreads();         // all warps done with buffer cur^1 reads
        if (kb + 1 < NKB) issue_tile(kb + 1, cur ^ 1);

        uint32_t ks_base = ks_b[cur];
        uint32_t vs_base = vs_b[cur];

        // --- S = Q K^T ---
        float sacc[8][4];
#pragma unroll
        for (int nt = 0; nt < 8; nt++)
#pragma unroll
            for (int i = 0; i < 4; i++) sacc[nt][i] = 0.f;

#pragma unroll
        for (int kk = 0; kk < 4; kk++) {
#pragma unroll
            for (int ntp = 0; ntp < 4; ntp++) {
                uint32_t d0, d1, d2, d3;
                ldsm_x4(d0, d1, d2, d3, ks_base + ntp * 16 * (QS_PITCH * 2) + kk * 32);
                mma_bf16(sacc[2 * ntp][0], sacc[2 * ntp][1], sacc[2 * ntp][2], sacc[2 * ntp][3],
                         qa[kk][0], qa[kk][1], qa[kk][2], qa[kk][3], d0, d1);
                mma_bf16(sacc[2 * ntp + 1][0], sacc[2 * ntp + 1][1], sacc[2 * ntp + 1][2], sacc[2 * ntp + 1][3],
                         qa[kk][0], qa[kk][1], qa[kk][2], qa[kk][3], d2, d3);
            }
        }

        // --- constant-shift exp + partial sums ---
#pragma unroll
        for (int nt = 0; nt < 8; nt++) {
            sacc[nt][0] = __expf(sacc[nt][0] - 8.f);
            sacc[nt][1] = __expf(sacc[nt][1] - 8.f);
            sacc[nt][2] = __expf(sacc[nt][2] - 8.f);
            sacc[nt][3] = __expf(sacc[nt][3] - 8.f);
            ls_lo += sacc[nt][0] + sacc[nt][1];
            ls_hi += sacc[nt][2] + sacc[nt][3];
        }

        // --- AV ---
#pragma unroll
        for (int kk = 0; kk < 4; kk++) {
            uint32_t pa0 = pack_bf16x2(sacc[2 * kk][0],     sacc[2 * kk][1]);
            uint32_t pa1 = pack_bf16x2(sacc[2 * kk][2],     sacc[2 * kk][3]);
            uint32_t pa2 = pack_bf16x2(sacc[2 * kk + 1][0], sacc[2 * kk + 1][1]);
            uint32_t pa3 = pack_bf16x2(sacc[2 * kk + 1][2], sacc[2 * kk + 1][3]);
            uint32_t vrow_a = vs_base + kk * 16 * (VS2_PITCH * 2);
#pragma unroll
            for (int vt = 0; vt < 8; vt++) {
                uint32_t d0, d1, d2, d3;
                ldsm_x4_trans(d0, d1, d2, d3, vrow_a + (wn * 128 + vt * 16) * 2);
                mma_bf16(acc[2 * vt][0], acc[2 * vt][1], acc[2 * vt][2], acc[2 * vt][3],
                         pa0, pa1, pa2, pa3, d0, d1);
                mma_bf16(acc[2 * vt + 1][0], acc[2 * vt + 1][1], acc[2 * vt + 1][2], acc[2 * vt + 1][3],
                         pa0, pa1, pa2, pa3, d2, d3);
            }
        }
    }

    // --- epilogue ---
    ls_lo += __shfl_xor_sync(0xffffffffu, ls_lo, 1);
    ls_lo += __shfl_xor_sync(0xffffffffu, ls_lo, 2);
    ls_hi += __shfl_xor_sync(0xffffffffu, ls_hi, 1);
    ls_hi += __shfl_xor_sync(0xffffffffu, ls_hi, 2);
    float inv_lo = 1.f / ls_lo, inv_hi = 1.f / ls_hi;

    int row_lo = qt * 64 + wm * 16 + (l >> 2);
    int col0   = ch * 256 + wn * 128 + 2 * (l & 3);
    __nv_bfloat16* av_lo = g_avb + ((size_t)b * LL + row_lo) * CC;
    __nv_bfloat16* av_hi = av_lo + 8 * CC;
#pragma unroll
    for (int nt = 0; nt < 16; nt++) {
        int c = col0 + nt * 8;
        *(uint32_t*)(av_lo + c) = pack_bf16x2(acc[nt][0] * inv_lo, acc[nt][1] * inv_lo);
        *(uint32_t*)(av_hi + c) = pack_bf16x2(acc[nt][2] * inv_hi, acc[nt][3] * inv_hi);
    }
}

// ---------------- kernel 3: output projection (bf16 HMMA, cp.async) --------
#define OUT_STAGE (2 * 128 * WS_PITCH * 2)   // A tile + B tile = 36864
#define OUT_SMEM  (2 * OUT_STAGE)
__global__ __launch_bounds__(256) void out_kernel(const float* __restrict__ x,
                                                  const float* __restrict__ bo,
                                                  const float* __restrict__ gamma,
                                                  float* __restrict__ out) {
    extern __shared__ __align__(16) char osm[];
    uint32_t sbase = (uint32_t)__cvta_generic_to_shared(osm);

    int b  = blockIdx.z;
    int ot = blockIdx.y;
    int lt = blockIdx.x;
    int t  = threadIdx.x;
    int w  = t >> 5, ln = t & 31;
    int wm = w & 3;
    int wn = w >> 2;
    int o0 = ot * 128;

    auto issue_stage = [&](int k0, int buf) {
        uint32_t as = sbase + buf * OUT_STAGE;
        uint32_t bs = as + 128 * WS_PITCH * 2;
        const char* ag = (const char*)(g_wob + (size_t)o0 * CC + k0);
        const char* bg = (const char*)(g_avb + ((size_t)b * LL + lt * 128) * CC + k0);
#pragma unroll
        for (int i = 0; i < 4; i++) {
            int e = t + 256 * i;
            int row = e >> 3, c = e & 7;
            cp_async16(as + row * (WS_PITCH * 2) + c * 16,
                       ag + (size_t)row * (CC * 2) + c * 16);
            cp_async16(bs + row * (WS_PITCH * 2) + c * 16,
                       bg + (size_t)row * (CC * 2) + c * 16);
        }
        cp_commit();
    };

    float acc[2][8][4];
#pragma unroll
    for (int mt = 0; mt < 2; mt++)
#pragma unroll
        for (int nt = 0; nt < 8; nt++)
#pragma unroll
            for (int i = 0; i < 4; i++) acc[mt][nt][i] = 0.f;

    uint32_t ab_lane = (uint32_t)(((ln & 7) + 8 * ((ln >> 3) & 1)) * (WS_PITCH * 2))
                     + 16 * ((ln >> 4) & 1) + (uint32_t)(wm * 32 * (WS_PITCH * 2));
    uint32_t bb_lane = (uint32_t)(128 * WS_PITCH * 2)
                     + (uint32_t)(((ln & 7) + 8 * ((ln >> 4) & 1)) * (WS_PITCH * 2))
                     + 16 * ((ln >> 3) & 1) + (uint32_t)(wn * 64 * (WS_PITCH * 2));

    issue_stage(0, 0);

    for (int k0 = 0; k0 < CC; k0 += 64) {
        int buf = (k0 >> 6) & 1;
        cp_wait<0>();
        __syncthreads();
        if (k0 + 64 < CC) issue_stage(k0 + 64, buf ^ 1);

        uint32_t ab = sbase + buf * OUT_STAGE + ab_lane;
        uint32_t bb = sbase + buf * OUT_STAGE + bb_lane;
#pragma unroll
        for (int kk = 0; kk < 4; kk++) {
            uint32_t a[2][4];
#pragma unroll
            for (int mt = 0; mt < 2; mt++)
                ldsm_x4(a[mt][0], a[mt][1], a[mt][2], a[mt][3],
                        ab + mt * 16 * (WS_PITCH * 2) + kk * 32);
#pragma unroll
            for (int ntp = 0; ntp < 4; ntp++) {
                uint32_t b0, b1, b2, b3;
                ldsm_x4(b0, b1, b2, b3, bb + ntp * 16 * (WS_PITCH * 2) + kk * 32);
#pragma unroll
                for (int mt = 0; mt < 2; mt++) {
                    mma_bf16(acc[mt][2 * ntp][0], acc[mt][2 * ntp][1],
                             acc[mt][2 * ntp][2], acc[mt][2 * ntp][3],
                             a[mt][0], a[mt][1], a[mt][2], a[mt][3], b0, b1);
                    mma_bf16(acc[mt][2 * ntp + 1][0], acc[mt][2 * ntp + 1][1],
                             acc[mt][2 * ntp + 1][2], acc[mt][2 * ntp + 1][3],
                             a[mt][0], a[mt][1], a[mt][2], a[mt][3], b2, b3);
                }
            }
        }
        __syncthreads();
    }

    float g = gamma[0];
    int cl = 2 * (ln & 3);
#pragma unroll
    for (int mt = 0; mt < 2; mt++) {
        int o_r = o0 + wm * 32 + mt * 16 + (ln >> 2);
        float b0v = bo[o_r], b1v = bo[o_r + 8];
#pragma unroll
        for (int nt = 0; nt < 8; nt++) {
            int lc = lt * 128 + wn * 64 + nt * 8 + cl;
            size_t base0 = ((size_t)b * CC + o_r) * LL + lc;
            size_t base1 = base0 + (size_t)8 * LL;
            float2 xv0 = *(const float2*)(x + base0);
            float2 xv1 = *(const float2*)(x + base1);
            float2 r0, r1;
            r0.x = g * (acc[mt][nt][0] + b0v) + xv0.x;
            r0.y = g * (acc[mt][nt][1] + b0v) + xv0.y;
            r1.x = g * (acc[mt][nt][2] + b1v) + xv1.x;
            r1.y = g * (acc[mt][nt][3] + b1v) + xv1.y;
            *(float2*)(out + base0) = r0;
            *(float2*)(out + base1) = r1;
        }
    }
}

// ---------------- launch ----------------------------------------------------
extern "C" void kernel_launch(void* const* d_in, const int* in_sizes, int n_in,
                              void* d_out, int out_size) {
    const float* x     = (const float*)d_in[0];
    const float* wq    = (const float*)d_in[1];
    const float* bq    = (const float*)d_in[2];
    const float* wk    = (const float*)d_in[3];
    const float* bk    = (const float*)d_in[4];
    const float* wv    = (const float*)d_in[5];
    const float* bv    = (const float*)d_in[6];
    const float* wo    = (const float*)d_in[7];
    const float* bo    = (const float*)d_in[8];
    const float* gamma = (const float*)d_in[9];
    float* out = (float*)d_out;

    cudaFuncSetAttribute(attn_kernel, cudaFuncAttributeMaxDynamicSharedMemorySize,
                         SM_ATTN_BYTES);
    cudaFuncSetAttribute(qkv_kernel, cudaFuncAttributeMaxDynamicSharedMemorySize,
                         QKV_SMEM);
    cudaFuncSetAttribute(out_kernel, cudaFuncAttributeMaxDynamicSharedMemorySize,
                         OUT_SMEM);

    prep_kernel<<<(CC * CC + 255) / 256 + 256, 256>>>(wq, bq, wk, bk, wv, bv, wo);
    xconv_kernel<<<((size_t)BB * CC * LL / 4) / 256, 256>>>(x);

    dim3 g1(LL / 128, MQKV / 128, BB);
    qkv_kernel<<<g1, 256, QKV_SMEM>>>();

    dim3 g2(LL / 64, 2, BB);
    attn_kernel<<<g2, 256, SM_ATTN_BYTES>>>();

    dim3 g3(LL / 128, CC / 128, BB);
    out_kernel<<<g3, 256, OUT_SMEM>>>(x, bo, gamma, out);
}